// round 1
// baseline (speedup 1.0000x reference)
#include <cuda_runtime.h>
#include <cstddef>
#include <cstdint>

// Problem dims
constexpr int BB = 4096;   // batch
constexpr int TT = 128;    // time
constexpr int HH = 156;    // hidden/nodes
constexpr int LL = 2;      // layers
constexpr int OO = 12;     // output len
constexpr int G4 = 4 * HH; // 624 (gates i,f,c,o concatenated)

// Scratch (device globals; each < 2 GB)
constexpr size_t XG_ELEMS = (size_t)TT * BB * G4;      // 327,155,712 floats (~1.22 GiB)
__device__ float g_xg0[XG_ELEMS];
__device__ float g_xg1[XG_ELEMS];
__device__ float g_ys[(size_t)BB * TT * HH];           // 81,788,928 floats (~312 MiB)

// ---------------- helpers ----------------
__device__ __forceinline__ float2 fma2(float2 d, float2 a, float2 b) {
    unsigned long long dd = *reinterpret_cast<unsigned long long*>(&d);
    unsigned long long aa = *reinterpret_cast<unsigned long long*>(&a);
    unsigned long long bb = *reinterpret_cast<unsigned long long*>(&b);
    asm("fma.rn.f32x2 %0, %1, %2, %0;" : "+l"(dd) : "l"(aa), "l"(bb));
    return *reinterpret_cast<float2*>(&dd);
}
__device__ __forceinline__ float sigmoidf_(float x) {
    return 1.0f / (1.0f + __expf(-x));
}

// ---------------- kernel 1: prelude XG = x @ Wcat_x^T + (bx+bh) ----------------
struct XArgs {
    const float* W[4];   // Wix, Wfx, Wcx, Wox   each [L,H,H]
    const float* bx[4];  // bix, bfx, bcx, box   each [L,H]
    const float* bh[4];  // bih, bfh, bch, boh   each [L,H]
};

constexpr int PRE_SMEM = 2 * 64 * 158 * 4; // 80,896 B

__global__ __launch_bounds__(256) void prelude_kernel(const float* __restrict__ x, XArgs A) {
    extern __shared__ float sm[];
    float* As = sm;             // [64][158]
    float* Bs = sm + 64 * 158;  // [64][158]
    const int l = blockIdx.z, nt = blockIdx.y, mt = blockIdx.x;
    const int tid = threadIdx.x;
    const int m0 = mt * 64, n0 = nt * 64;

    // A tile: 64 rows of x (row = b*T + t), 156 floats each (78 float2)
    for (int i = tid; i < 64 * 78; i += 256) {
        int r = i / 78, c = i - r * 78;
        *(float2*)(As + r * 158 + 2 * c) =
            *(const float2*)(x + (size_t)(m0 + r) * HH + 2 * c);
    }
    // B tile: rows n0..n0+63 of concatenated gate weight [624][156]
    for (int i = tid; i < 64 * 78; i += 256) {
        int r = i / 78, c = i - r * 78;
        int n = n0 + r;
        float2 v = make_float2(0.f, 0.f);
        if (n < G4) {
            int g = n / HH, o = n - g * HH;
            v = *(const float2*)(A.W[g] + ((size_t)l * HH + o) * HH + 2 * c);
        }
        *(float2*)(Bs + r * 158 + 2 * c) = v;
    }
    __syncthreads();

    const int tx = tid & 15, ty = tid >> 4;
    float2 acc[4][4];
#pragma unroll
    for (int i = 0; i < 4; i++)
#pragma unroll
        for (int j = 0; j < 4; j++) acc[i][j] = make_float2(0.f, 0.f);

#pragma unroll 2
    for (int kp = 0; kp < 78; ++kp) {
        float2 a2[4], b2[4];
#pragma unroll
        for (int i = 0; i < 4; i++) a2[i] = *(const float2*)(As + (ty + 16 * i) * 158 + 2 * kp);
#pragma unroll
        for (int j = 0; j < 4; j++) b2[j] = *(const float2*)(Bs + (tx + 16 * j) * 158 + 2 * kp);
#pragma unroll
        for (int i = 0; i < 4; i++)
#pragma unroll
            for (int j = 0; j < 4; j++) acc[i][j] = fma2(acc[i][j], a2[i], b2[j]);
    }

    float* xg = (l == 0) ? g_xg0 : g_xg1;
#pragma unroll
    for (int i = 0; i < 4; i++) {
        int m = m0 + ty + 16 * i;
        int b = m >> 7, t = m & 127;   // m = b*T + t, T=128
        size_t rb = ((size_t)t * BB + b) * G4;
#pragma unroll
        for (int j = 0; j < 4; j++) {
            int n = n0 + tx + 16 * j;
            if (n < G4) {
                int g = n / HH, o = n - g * HH;
                xg[rb + n] = acc[i][j].x + acc[i][j].y +
                             A.bx[g][l * HH + o] + A.bh[g][l * HH + o];
            }
        }
    }
}

// ---------------- kernel 2: full recurrence (one launch, per-block time loop) ----------------
struct HArgs {
    const float* W[4];   // Wih, Wfh, Wch, Woh  each [L,H,H]
};

constexpr int RS = 158;                 // smem row stride (floats)
constexpr int SADJ_F = 156 * RS;        // adj^T cache
constexpr int BUF_F = 64 * RS;          // one state buffer
constexpr int RSMEM = (SADJ_F + 3 * BUF_F) * 4;  // 219,936 B

__global__ __launch_bounds__(512, 1) void recur_kernel(
        const float* __restrict__ adj, HArgs A,
        const float* __restrict__ gw1, const float* __restrict__ gw2,
        float* __restrict__ out) {
    extern __shared__ float sm[];
    float* sadj = sm;                // sadj[o][k] = adj[o][k] (row-major adj as-is)
    float* bufs = sm + SADJ_F;
    const int l = blockIdx.y;
    const int r0 = blockIdx.x * 64;  // this block's 64 batch rows
    const int tid = threadIdx.x;
    const int tx = tid & 31, ty = tid >> 5;   // ty in [0,16)

    for (int i = tid; i < 156 * 78; i += 512) {
        int r = i / 78, c = i - r * 78;
        *(float2*)(sadj + r * RS + 2 * c) = *(const float2*)(adj + r * HH + 2 * c);
    }
    for (int i = tid; i < 3 * BUF_F; i += 512) bufs[i] = 0.f;
    __syncthreads();

    float* sh  = bufs;              // h  (swaps with stp each step)
    float* scc = bufs + BUF_F;      // c  (fixed, updated in place)
    float* stp = bufs + 2 * BUF_F;  // temp / next h

    const float c1 = gw1[l], c2 = gw2[l];
    const float* xg = (l == 0) ? g_xg0 : g_xg1;

    // GCN half-step: OUT[m][o] = act( w * dot(IN[m][:], adj[o][:]) )
    auto gcnp = [&](const float* IN, float* OUT, float w, bool rl) {
        float2 acc[4][5];
#pragma unroll
        for (int i = 0; i < 4; i++)
#pragma unroll
            for (int j = 0; j < 5; j++) acc[i][j] = make_float2(0.f, 0.f);
#pragma unroll 2
        for (int kp = 0; kp < 78; ++kp) {
            float2 a2[4], b2[5];
#pragma unroll
            for (int i = 0; i < 4; i++) a2[i] = *(const float2*)(IN + (ty + 16 * i) * RS + 2 * kp);
#pragma unroll
            for (int j = 0; j < 5; j++) b2[j] = *(const float2*)(sadj + (tx + 32 * j) * RS + 2 * kp);
#pragma unroll
            for (int i = 0; i < 4; i++)
#pragma unroll
                for (int j = 0; j < 5; j++) acc[i][j] = fma2(acc[i][j], a2[i], b2[j]);
        }
#pragma unroll
        for (int j = 0; j < 5; j++) {
            int o = tx + 32 * j;
            if (o < HH) {
#pragma unroll
                for (int i = 0; i < 4; i++) {
                    int m = ty + 16 * i;
                    float v = w * (acc[i][j].x + acc[i][j].y);
                    v = rl ? fmaxf(v, 0.f) : sigmoidf_(v);
                    OUT[m * RS + o] = v;
                }
            }
        }
    };

    auto gates = [&](int t) {
#pragma unroll 1
        for (int j = 0; j < 5; ++j) {
            int o = tx + 32 * j;
            bool ov = (o < HH);
            int oc = ov ? o : 0;
            const float* wr0 = A.W[0] + ((size_t)l * HH + oc) * HH;
            const float* wr1 = A.W[1] + ((size_t)l * HH + oc) * HH;
            const float* wr2 = A.W[2] + ((size_t)l * HH + oc) * HH;
            const float* wr3 = A.W[3] + ((size_t)l * HH + oc) * HH;
            float2 acc[4][4];
#pragma unroll
            for (int i = 0; i < 4; i++)
#pragma unroll
                for (int g = 0; g < 4; g++) acc[i][g] = make_float2(0.f, 0.f);
#pragma unroll 2
            for (int kp = 0; kp < 78; ++kp) {
                float2 a2[4];
#pragma unroll
                for (int i = 0; i < 4; i++) a2[i] = *(const float2*)(sh + (ty + 16 * i) * RS + 2 * kp);
                float2 w0 = *(const float2*)(wr0 + 2 * kp);
                float2 w1v = *(const float2*)(wr1 + 2 * kp);
                float2 w2v = *(const float2*)(wr2 + 2 * kp);
                float2 w3v = *(const float2*)(wr3 + 2 * kp);
#pragma unroll
                for (int i = 0; i < 4; i++) {
                    acc[i][0] = fma2(acc[i][0], a2[i], w0);
                    acc[i][1] = fma2(acc[i][1], a2[i], w1v);
                    acc[i][2] = fma2(acc[i][2], a2[i], w2v);
                    acc[i][3] = fma2(acc[i][3], a2[i], w3v);
                }
            }
            if (ov) {
#pragma unroll
                for (int i = 0; i < 4; i++) {
                    int m = ty + 16 * i;
                    int row = r0 + m;
                    size_t xb = ((size_t)t * BB + row) * G4;
                    float pi = acc[i][0].x + acc[i][0].y + xg[xb + o];
                    float pf = acc[i][1].x + acc[i][1].y + xg[xb + HH + o];
                    float pc = acc[i][2].x + acc[i][2].y + xg[xb + 2 * HH + o];
                    float po = acc[i][3].x + acc[i][3].y + xg[xb + 3 * HH + o];
                    float it = sigmoidf_(pi);
                    float ft = sigmoidf_(pf);
                    float ot = sigmoidf_(po);
                    float cb = tanhf(pc);
                    float ct = ft * scc[m * RS + o] + it * cb;
                    scc[m * RS + o] = ct;
                    float hn = ot * tanhf(ct);
                    stp[m * RS + o] = hn;
                    if (l == 1) g_ys[((size_t)row * TT + t) * HH + o] = hn;
                }
            }
        }
    };

    for (int t = 0; t < TT; ++t) {
        if (t > 0) {
            gcnp(sh,  stp, c1, true);  __syncthreads();
            gcnp(stp, sh,  c2, false); __syncthreads();  // sh = gcn(h)
            gcnp(scc, stp, c1, true);  __syncthreads();
            gcnp(stp, scc, c2, false); __syncthreads();  // scc = gcn(c)
        }
        gates(t);
        __syncthreads();
        float* tsw = sh; sh = stp; stp = tsw;            // new h becomes h
    }

    // final states -> h_n, c_n (after the out block)
    constexpr size_t OUT0 = (size_t)BB * OO * HH;        // 7,667,712
    constexpr size_t HN   = (size_t)LL * BB * HH;        // 1,277,952
    for (int i = tid; i < 64 * HH; i += 512) {
        int m = i / HH, o = i - m * HH;
        int row = r0 + m;
        size_t off = ((size_t)l * BB + row) * HH + o;
        out[OUT0 + off]      = sh[m * RS + o];
        out[OUT0 + HN + off] = scc[m * RS + o];
    }
}

// ---------------- kernel 3: out[b, f*12+j] = sum_t ys_flat[b, f*128+t]*Wout[j,t] + bout[j] ----
constexpr int YROW = TT * HH;  // 19968
constexpr int OSMEM = (YROW + OO * TT + OO) * 4;  // 86,064 B

__global__ __launch_bounds__(256) void out_kernel(const float* __restrict__ Wout,
                                                  const float* __restrict__ bout,
                                                  float* __restrict__ out) {
    extern __shared__ float sm[];
    float* sy = sm;               // [19968] this batch row of ys (flat)
    float* sw = sm + YROW;        // [12*128]
    float* sb = sw + OO * TT;     // [12]
    const int b = blockIdx.x;
    const int tid = threadIdx.x;
    const float* yb = g_ys + (size_t)b * YROW;
    for (int i = tid; i < YROW / 4; i += 256) ((float4*)sy)[i] = ((const float4*)yb)[i];
    for (int i = tid; i < OO * TT; i += 256) sw[i] = Wout[i];
    if (tid < OO) sb[tid] = bout[tid];
    __syncthreads();
    for (int idx = tid; idx < HH * OO; idx += 256) {
        int f = idx / OO, jj = idx - f * OO;
        const float* yr = sy + f * TT;
        const float* wr = sw + jj * TT;
        float2 a = make_float2(0.f, 0.f);
#pragma unroll 4
        for (int p = 0; p < TT / 2; ++p)
            a = fma2(a, *(const float2*)(yr + 2 * p), *(const float2*)(wr + 2 * p));
        out[(size_t)b * (HH * OO) + idx] = a.x + a.y + sb[jj];
    }
}

// ---------------- launcher ----------------
extern "C" void kernel_launch(void* const* d_in, const int* in_sizes, int n_in,
                              void* d_out, int out_size) {
    const float* x   = (const float*)d_in[0];
    const float* adj = (const float*)d_in[1];

    XArgs xa;
    xa.W[0] = (const float*)d_in[2];  xa.bx[0] = (const float*)d_in[3];
    xa.W[1] = (const float*)d_in[6];  xa.bx[1] = (const float*)d_in[7];
    xa.W[2] = (const float*)d_in[10]; xa.bx[2] = (const float*)d_in[11];
    xa.W[3] = (const float*)d_in[14]; xa.bx[3] = (const float*)d_in[15];
    xa.bh[0] = (const float*)d_in[5];
    xa.bh[1] = (const float*)d_in[9];
    xa.bh[2] = (const float*)d_in[13];
    xa.bh[3] = (const float*)d_in[17];

    HArgs ha;
    ha.W[0] = (const float*)d_in[4];
    ha.W[1] = (const float*)d_in[8];
    ha.W[2] = (const float*)d_in[12];
    ha.W[3] = (const float*)d_in[16];

    const float* gw1  = (const float*)d_in[18];
    const float* gw2  = (const float*)d_in[19];
    const float* Wout = (const float*)d_in[20];
    const float* bout = (const float*)d_in[21];
    float* out = (float*)d_out;

    cudaFuncSetAttribute(prelude_kernel, cudaFuncAttributeMaxDynamicSharedMemorySize, PRE_SMEM);
    cudaFuncSetAttribute(recur_kernel,   cudaFuncAttributeMaxDynamicSharedMemorySize, RSMEM);
    cudaFuncSetAttribute(out_kernel,     cudaFuncAttributeMaxDynamicSharedMemorySize, OSMEM);

    dim3 pg(BB * TT / 64, 10, LL);           // 8192 x 10 x 2 tiles
    prelude_kernel<<<pg, 256, PRE_SMEM>>>(x, xa);

    dim3 rg(BB / 64, LL);                    // 64 x 2 = 128 persistent blocks
    recur_kernel<<<rg, 512, RSMEM>>>(adj, ha, gw1, gw2, out);

    out_kernel<<<BB, 256, OSMEM>>>(Wout, bout, out);
}

// round 2
// speedup vs baseline: 1.8111x; 1.8111x over previous
#include <cuda_runtime.h>
#include <cstddef>
#include <cstdint>

// Problem dims
constexpr int BB = 4096;   // batch
constexpr int TT = 128;    // time
constexpr int HH = 156;    // hidden/nodes
constexpr int LL = 2;      // layers
constexpr int OO = 12;     // output len
constexpr int G4 = 4 * HH; // 624 (gates i,f,c,o concatenated)

// Scratch (device globals; each < 2 GB)
constexpr size_t XG_ELEMS = (size_t)TT * BB * G4;      // ~1.22 GiB
__device__ float g_xg0[XG_ELEMS];
__device__ float g_xg1[XG_ELEMS];
__device__ float g_ys[(size_t)BB * TT * HH];           // ~312 MiB

// Transposed recurrent weights: g_wt[g][l][k][o_pad=192]  (~0.96 MB)
constexpr int OPAD = 192;
__device__ float g_wt[4 * LL * HH * OPAD];

// ---------------- helpers ----------------
__device__ __forceinline__ float2 fma2(float2 d, float2 a, float2 b) {
    unsigned long long dd = *reinterpret_cast<unsigned long long*>(&d);
    unsigned long long aa = *reinterpret_cast<unsigned long long*>(&a);
    unsigned long long bb = *reinterpret_cast<unsigned long long*>(&b);
    asm("fma.rn.f32x2 %0, %1, %2, %0;" : "+l"(dd) : "l"(aa), "l"(bb));
    return *reinterpret_cast<float2*>(&dd);
}
__device__ __forceinline__ float sigmoidf_(float x) {
    return __fdividef(1.0f, 1.0f + __expf(-x));
}
__device__ __forceinline__ float tanhf_fast(float x) {
    float ax = fabsf(x);
    float e = __expf(-2.0f * ax);
    float t = __fdividef(1.0f - e, 1.0f + e);
    return copysignf(t, x);
}

// ---------------- kernel 1: prelude XG = x @ Wcat_x^T + (bx+bh) ----------------
struct XArgs {
    const float* W[4];   // Wix, Wfx, Wcx, Wox   each [L,H,H]
    const float* bx[4];  // bix, bfx, bcx, box   each [L,H]
    const float* bh[4];  // bih, bfh, bch, boh   each [L,H]
};

constexpr int PRE_SMEM = 2 * 64 * 158 * 4; // 80,896 B

__global__ __launch_bounds__(256) void prelude_kernel(const float* __restrict__ x, XArgs A) {
    extern __shared__ float sm[];
    float* As = sm;             // [64][158]
    float* Bs = sm + 64 * 158;  // [64][158]
    const int l = blockIdx.z, nt = blockIdx.y, mt = blockIdx.x;
    const int tid = threadIdx.x;
    const int m0 = mt * 64, n0 = nt * 64;

    for (int i = tid; i < 64 * 78; i += 256) {
        int r = i / 78, c = i - r * 78;
        *(float2*)(As + r * 158 + 2 * c) =
            *(const float2*)(x + (size_t)(m0 + r) * HH + 2 * c);
    }
    for (int i = tid; i < 64 * 78; i += 256) {
        int r = i / 78, c = i - r * 78;
        int n = n0 + r;
        float2 v = make_float2(0.f, 0.f);
        if (n < G4) {
            int g = n / HH, o = n - g * HH;
            v = *(const float2*)(A.W[g] + ((size_t)l * HH + o) * HH + 2 * c);
        }
        *(float2*)(Bs + r * 158 + 2 * c) = v;
    }
    __syncthreads();

    const int tx = tid & 15, ty = tid >> 4;
    float2 acc[4][4];
#pragma unroll
    for (int i = 0; i < 4; i++)
#pragma unroll
        for (int j = 0; j < 4; j++) acc[i][j] = make_float2(0.f, 0.f);

#pragma unroll 2
    for (int kp = 0; kp < 78; ++kp) {
        float2 a2[4], b2[4];
#pragma unroll
        for (int i = 0; i < 4; i++) a2[i] = *(const float2*)(As + (ty + 16 * i) * 158 + 2 * kp);
#pragma unroll
        for (int j = 0; j < 4; j++) b2[j] = *(const float2*)(Bs + (tx + 16 * j) * 158 + 2 * kp);
#pragma unroll
        for (int i = 0; i < 4; i++)
#pragma unroll
            for (int j = 0; j < 4; j++) acc[i][j] = fma2(acc[i][j], a2[i], b2[j]);
    }

    float* xg = (l == 0) ? g_xg0 : g_xg1;
#pragma unroll
    for (int i = 0; i < 4; i++) {
        int m = m0 + ty + 16 * i;
        int b = m >> 7, t = m & 127;   // m = b*T + t, T=128
        size_t rb = ((size_t)t * BB + b) * G4;
#pragma unroll
        for (int j = 0; j < 4; j++) {
            int n = n0 + tx + 16 * j;
            if (n < G4) {
                int g = n / HH, o = n - g * HH;
                xg[rb + n] = acc[i][j].x + acc[i][j].y +
                             A.bx[g][l * HH + o] + A.bh[g][l * HH + o];
            }
        }
    }
}

// ---------------- kernel 1b: transpose recurrent weights into [g][l][k][OPAD] ----
struct HArgs {
    const float* W[4];   // Wih, Wfh, Wch, Woh  each [L,H,H]
};

__global__ __launch_bounds__(256) void wtrans_kernel(HArgs A) {
    int idx = blockIdx.x * 256 + threadIdx.x;
    constexpr int TOTAL = 4 * LL * HH * OPAD;
    if (idx >= TOTAL) return;
    int o = idx % OPAD;
    int r = idx / OPAD;
    int k = r % HH;
    int r2 = r / HH;
    int l = r2 % LL;
    int g = r2 / LL;
    float v = 0.f;
    if (o < HH) v = A.W[g][((size_t)l * HH + o) * HH + k];
    g_wt[idx] = v;
}

// ---------------- kernel 2: full recurrence (one launch, per-block time loop) ----------------
constexpr int RS = 158;                 // smem row stride (floats)
constexpr int SADJ_F = 156 * RS;        // adj cache
constexpr int BUF_F = 64 * RS;          // one state buffer
constexpr int RSMEM = (SADJ_F + 3 * BUF_F) * 4;  // 219,936 B

__global__ __launch_bounds__(512, 1) void recur_kernel(
        const float* __restrict__ adj,
        const float* __restrict__ gw1, const float* __restrict__ gw2,
        float* __restrict__ out) {
    extern __shared__ float sm[];
    float* sadj = sm;                // sadj[o][k] = adj[o][k]
    float* bufs = sm + SADJ_F;
    const int l = blockIdx.y;
    const int r0 = blockIdx.x * 64;  // this block's 64 batch rows
    const int tid = threadIdx.x;
    const int tx = tid & 31, ty = tid >> 5;   // ty in [0,16)

    for (int i = tid; i < 156 * 78; i += 512) {
        int r = i / 78, c = i - r * 78;
        *(float2*)(sadj + r * RS + 2 * c) = *(const float2*)(adj + r * HH + 2 * c);
    }
    for (int i = tid; i < 3 * BUF_F; i += 512) bufs[i] = 0.f;
    __syncthreads();

    float* sh  = bufs;              // h  (swaps with stp each step)
    float* scc = bufs + BUF_F;      // c  (fixed, updated in place)
    float* stp = bufs + 2 * BUF_F;  // temp / next h

    const float c1 = gw1[l], c2 = gw2[l];
    const float* xg = (l == 0) ? g_xg0 : g_xg1;

    // GCN half-step: OUT[m][o] = act( w * dot(IN[m][:], adj[o][:]) )   (all-SMEM)
    auto gcnp = [&](const float* IN, float* OUT, float w, bool rl) {
        float2 acc[4][5];
#pragma unroll
        for (int i = 0; i < 4; i++)
#pragma unroll
            for (int j = 0; j < 5; j++) acc[i][j] = make_float2(0.f, 0.f);
#pragma unroll 2
        for (int kp = 0; kp < 78; ++kp) {
            float2 a2[4], b2[5];
#pragma unroll
            for (int i = 0; i < 4; i++) a2[i] = *(const float2*)(IN + (ty + 16 * i) * RS + 2 * kp);
#pragma unroll
            for (int j = 0; j < 5; j++) b2[j] = *(const float2*)(sadj + (tx + 32 * j) * RS + 2 * kp);
#pragma unroll
            for (int i = 0; i < 4; i++)
#pragma unroll
                for (int j = 0; j < 5; j++) acc[i][j] = fma2(acc[i][j], a2[i], b2[j]);
        }
#pragma unroll
        for (int j = 0; j < 5; j++) {
            int o = tx + 32 * j;
            if (o < HH) {
#pragma unroll
                for (int i = 0; i < 4; i++) {
                    int m = ty + 16 * i;
                    float v = w * (acc[i][j].x + acc[i][j].y);
                    v = rl ? fmaxf(v, 0.f) : sigmoidf_(v);
                    OUT[m * RS + o] = v;
                }
            }
        }
    };

    // gates: outer-product over k. Lanes own an o-PAIR (coalesced weight loads);
    // h[m][k] is a warp-uniform SMEM broadcast.
    auto gates = [&](int t) {
#pragma unroll 1
        for (int j = 0; j < 3; ++j) {
            const int o0 = 2 * (tx + 32 * j);   // even, in [0, 190]
            const float* w0p = g_wt + (size_t)((0 * LL + l) * HH) * OPAD + o0;
            const float* w1p = g_wt + (size_t)((1 * LL + l) * HH) * OPAD + o0;
            const float* w2p = g_wt + (size_t)((2 * LL + l) * HH) * OPAD + o0;
            const float* w3p = g_wt + (size_t)((3 * LL + l) * HH) * OPAD + o0;
            float2 acc[4][4];
#pragma unroll
            for (int i = 0; i < 4; i++)
#pragma unroll
                for (int g = 0; g < 4; g++) acc[i][g] = make_float2(0.f, 0.f);
#pragma unroll 2
            for (int k = 0; k < HH; ++k) {
                float2 wv0 = *(const float2*)(w0p + (size_t)k * OPAD);
                float2 wv1 = *(const float2*)(w1p + (size_t)k * OPAD);
                float2 wv2 = *(const float2*)(w2p + (size_t)k * OPAD);
                float2 wv3 = *(const float2*)(w3p + (size_t)k * OPAD);
                float2 a2[4];
#pragma unroll
                for (int i = 0; i < 4; i++) {
                    float a = sh[(ty + 16 * i) * RS + k];
                    a2[i] = make_float2(a, a);
                }
#pragma unroll
                for (int i = 0; i < 4; i++) {
                    acc[i][0] = fma2(acc[i][0], a2[i], wv0);
                    acc[i][1] = fma2(acc[i][1], a2[i], wv1);
                    acc[i][2] = fma2(acc[i][2], a2[i], wv2);
                    acc[i][3] = fma2(acc[i][3], a2[i], wv3);
                }
            }
            if (o0 < HH) {      // HH even, so o0 < HH ⟺ both pair slots valid
#pragma unroll
                for (int i = 0; i < 4; i++) {
                    int m = ty + 16 * i;
                    int row = r0 + m;
                    size_t xb = ((size_t)t * BB + row) * G4;
                    float2 xi = *(const float2*)(xg + xb + o0);
                    float2 xf = *(const float2*)(xg + xb + HH + o0);
                    float2 xc = *(const float2*)(xg + xb + 2 * HH + o0);
                    float2 xo = *(const float2*)(xg + xb + 3 * HH + o0);
                    float2 cold = *(const float2*)(scc + m * RS + o0);
                    float2 ct, hn;
                    {
                        float it = sigmoidf_(acc[i][0].x + xi.x);
                        float ft = sigmoidf_(acc[i][1].x + xf.x);
                        float cb = tanhf_fast(acc[i][2].x + xc.x);
                        float ot = sigmoidf_(acc[i][3].x + xo.x);
                        ct.x = ft * cold.x + it * cb;
                        hn.x = ot * tanhf_fast(ct.x);
                    }
                    {
                        float it = sigmoidf_(acc[i][0].y + xi.y);
                        float ft = sigmoidf_(acc[i][1].y + xf.y);
                        float cb = tanhf_fast(acc[i][2].y + xc.y);
                        float ot = sigmoidf_(acc[i][3].y + xo.y);
                        ct.y = ft * cold.y + it * cb;
                        hn.y = ot * tanhf_fast(ct.y);
                    }
                    *(float2*)(scc + m * RS + o0) = ct;
                    *(float2*)(stp + m * RS + o0) = hn;
                    if (l == 1)
                        *(float2*)(g_ys + ((size_t)row * TT + t) * HH + o0) = hn;
                }
            }
        }
    };

    for (int t = 0; t < TT; ++t) {
        if (t > 0) {
            gcnp(sh,  stp, c1, true);  __syncthreads();
            gcnp(stp, sh,  c2, false); __syncthreads();  // sh = gcn(h)
            gcnp(scc, stp, c1, true);  __syncthreads();
            gcnp(stp, scc, c2, false); __syncthreads();  // scc = gcn(c)
        }
        gates(t);
        __syncthreads();
        float* tsw = sh; sh = stp; stp = tsw;            // new h becomes h
    }

    // final states -> h_n, c_n (after the out block)
    constexpr size_t OUT0 = (size_t)BB * OO * HH;        // 7,667,712
    constexpr size_t HN   = (size_t)LL * BB * HH;        // 1,277,952
    for (int i = tid; i < 64 * HH; i += 512) {
        int m = i / HH, o = i - m * HH;
        int row = r0 + m;
        size_t off = ((size_t)l * BB + row) * HH + o;
        out[OUT0 + off]      = sh[m * RS + o];
        out[OUT0 + HN + off] = scc[m * RS + o];
    }
}

// ---------------- kernel 3: out[b, f*12+j] = sum_t ys_flat[b, f*128+t]*Wout[j,t] + bout[j] ----
constexpr int YROW = TT * HH;  // 19968
constexpr int OSMEM = (YROW + OO * TT + OO) * 4;  // 86,064 B

__global__ __launch_bounds__(256) void out_kernel(const float* __restrict__ Wout,
                                                  const float* __restrict__ bout,
                                                  float* __restrict__ out) {
    extern __shared__ float sm[];
    float* sy = sm;               // [19968] this batch row of ys (flat)
    float* sw = sm + YROW;        // [12*128]
    float* sb = sw + OO * TT;     // [12]
    const int b = blockIdx.x;
    const int tid = threadIdx.x;
    const float* yb = g_ys + (size_t)b * YROW;
    for (int i = tid; i < YROW / 4; i += 256) ((float4*)sy)[i] = ((const float4*)yb)[i];
    for (int i = tid; i < OO * TT; i += 256) sw[i] = Wout[i];
    if (tid < OO) sb[tid] = bout[tid];
    __syncthreads();
    for (int idx = tid; idx < HH * OO; idx += 256) {
        int f = idx / OO, jj = idx - f * OO;
        const float* yr = sy + f * TT;
        const float* wr = sw + jj * TT;
        float2 a = make_float2(0.f, 0.f);
#pragma unroll 4
        for (int p = 0; p < TT / 2; ++p)
            a = fma2(a, *(const float2*)(yr + 2 * p), *(const float2*)(wr + 2 * p));
        out[(size_t)b * (HH * OO) + idx] = a.x + a.y + sb[jj];
    }
}

// ---------------- launcher ----------------
extern "C" void kernel_launch(void* const* d_in, const int* in_sizes, int n_in,
                              void* d_out, int out_size) {
    const float* x   = (const float*)d_in[0];
    const float* adj = (const float*)d_in[1];

    XArgs xa;
    xa.W[0] = (const float*)d_in[2];  xa.bx[0] = (const float*)d_in[3];
    xa.W[1] = (const float*)d_in[6];  xa.bx[1] = (const float*)d_in[7];
    xa.W[2] = (const float*)d_in[10]; xa.bx[2] = (const float*)d_in[11];
    xa.W[3] = (const float*)d_in[14]; xa.bx[3] = (const float*)d_in[15];
    xa.bh[0] = (const float*)d_in[5];
    xa.bh[1] = (const float*)d_in[9];
    xa.bh[2] = (const float*)d_in[13];
    xa.bh[3] = (const float*)d_in[17];

    HArgs ha;
    ha.W[0] = (const float*)d_in[4];
    ha.W[1] = (const float*)d_in[8];
    ha.W[2] = (const float*)d_in[12];
    ha.W[3] = (const float*)d_in[16];

    const float* gw1  = (const float*)d_in[18];
    const float* gw2  = (const float*)d_in[19];
    const float* Wout = (const float*)d_in[20];
    const float* bout = (const float*)d_in[21];
    float* out = (float*)d_out;

    cudaFuncSetAttribute(prelude_kernel, cudaFuncAttributeMaxDynamicSharedMemorySize, PRE_SMEM);
    cudaFuncSetAttribute(recur_kernel,   cudaFuncAttributeMaxDynamicSharedMemorySize, RSMEM);
    cudaFuncSetAttribute(out_kernel,     cudaFuncAttributeMaxDynamicSharedMemorySize, OSMEM);

    dim3 pg(BB * TT / 64, 10, LL);           // 8192 x 10 x 2 tiles
    prelude_kernel<<<pg, 256, PRE_SMEM>>>(x, xa);

    constexpr int WT_TOTAL = 4 * LL * HH * OPAD;
    wtrans_kernel<<<(WT_TOTAL + 255) / 256, 256>>>(ha);

    dim3 rg(BB / 64, LL);                    // 64 x 2 = 128 persistent blocks
    recur_kernel<<<rg, 512, RSMEM>>>(adj, gw1, gw2, out);

    out_kernel<<<BB, 256, OSMEM>>>(Wout, bout, out);
}

// round 3
// speedup vs baseline: 2.4108x; 1.3312x over previous
#include <cuda_runtime.h>
#include <cstddef>
#include <cstdint>

// Problem dims
constexpr int BB = 4096;   // batch
constexpr int TT = 128;    // time
constexpr int HH = 156;    // hidden/nodes
constexpr int LL = 2;      // layers
constexpr int OO = 12;     // output len
constexpr int G4 = 4 * HH; // 624
constexpr int NP = 640;    // padded gate width for prelude

// Scratch (device globals)
constexpr size_t XG_ELEMS = (size_t)TT * BB * G4;      // ~1.22 GiB each
__device__ float g_xg0[XG_ELEMS];
__device__ float g_xg1[XG_ELEMS];
__device__ float g_ys[(size_t)BB * TT * HH];           // ~312 MiB

// Preprocessed weights
__device__ float  g_wxt[LL * HH * NP];        // x-weights transposed: [l][k][n(640)]
__device__ float  g_bsum[LL * NP];            // bx+bh concatenated:   [l][n(640)]
__device__ float  g_adjt[HH * 160];           // adj transposed:       [k][o(160)]
__device__ float4 g_wp4[LL * HH * 2 * 96];    // h-weights packed:     [l][k][s][op]

// ---------------- helpers ----------------
__device__ __forceinline__ float2 fma2(float2 d, float2 a, float2 b) {
    unsigned long long dd = *reinterpret_cast<unsigned long long*>(&d);
    unsigned long long aa = *reinterpret_cast<unsigned long long*>(&a);
    unsigned long long bb = *reinterpret_cast<unsigned long long*>(&b);
    asm("fma.rn.f32x2 %0, %1, %2, %0;" : "+l"(dd) : "l"(aa), "l"(bb));
    return *reinterpret_cast<float2*>(&dd);
}
__device__ __forceinline__ float sigmoidf_(float x) {
    return __fdividef(1.0f, 1.0f + __expf(-x));
}
__device__ __forceinline__ float tanhf_fast(float x) {
    float ax = fabsf(x);
    float e = __expf(-2.0f * ax);
    float t = __fdividef(1.0f - e, 1.0f + e);
    return copysignf(t, x);
}

struct XArgs {
    const float* W[4];   // Wix, Wfx, Wcx, Wox   each [L,H,H]
    const float* bx[4];
    const float* bh[4];
};
struct HArgs {
    const float* W[4];   // Wih, Wfh, Wch, Woh  each [L,H,H]
};

// ---------------- setup kernels (one-time transposes; trivial cost) ----------------
__global__ __launch_bounds__(256) void setup_wxt(XArgs A) {
    int idx = blockIdx.x * 256 + threadIdx.x;
    if (idx >= LL * HH * NP) return;
    int n = idx % NP, k = (idx / NP) % HH, l = idx / (NP * HH);
    float v = 0.f;
    if (n < G4) { int g = n / HH, o = n % HH; v = A.W[g][((size_t)l * HH + o) * HH + k]; }
    g_wxt[idx] = v;
}
__global__ __launch_bounds__(256) void setup_bsum(XArgs A) {
    int idx = blockIdx.x * 256 + threadIdx.x;
    if (idx >= LL * NP) return;
    int n = idx % NP, l = idx / NP;
    float v = 0.f;
    if (n < G4) { int g = n / HH, o = n % HH; v = A.bx[g][l * HH + o] + A.bh[g][l * HH + o]; }
    g_bsum[idx] = v;
}
__global__ __launch_bounds__(256) void setup_adjt(const float* __restrict__ adj) {
    int idx = blockIdx.x * 256 + threadIdx.x;
    if (idx >= HH * 160) return;
    int o = idx % 160, k = idx / 160;
    g_adjt[idx] = (o < HH) ? adj[o * HH + k] : 0.f;
}
__global__ __launch_bounds__(256) void setup_wp4(HArgs A) {
    int idx = blockIdx.x * 256 + threadIdx.x;
    if (idx >= LL * HH * 2 * 96) return;
    int op = idx % 96, s = (idx / 96) % 2, k = (idx / 192) % HH, l = idx / (192 * HH);
    int o0 = 2 * op, ga = 2 * s, gb = 2 * s + 1;
    auto w = [&](int g, int o) -> float {
        return (o < HH) ? A.W[g][((size_t)l * HH + o) * HH + k] : 0.f;
    };
    g_wp4[idx] = make_float4(w(ga, o0), w(ga, o0 + 1), w(gb, o0), w(gb, o0 + 1));
}

// ---------------- kernel 1: prelude XG = x @ Wcat_x^T + (bx+bh) ----------------
// broadcast-A x coalesced-B outer product; no smem, no syncs.
__global__ __launch_bounds__(256) void prelude2(const float* __restrict__ x) {
    const int l = blockIdx.z, nt = blockIdx.y;
    const int m0 = blockIdx.x * 64;
    const int lane = threadIdx.x & 31, wp = threadIdx.x >> 5;   // 8 warps
    const float* __restrict__ wb = g_wxt + (size_t)l * HH * NP + nt * 128 + 4 * lane;
    const float* __restrict__ xr = x + (size_t)(m0 + wp) * HH;

    float2 acc[8][2];
#pragma unroll
    for (int i = 0; i < 8; i++) { acc[i][0] = make_float2(0.f, 0.f); acc[i][1] = make_float2(0.f, 0.f); }

#pragma unroll 2
    for (int k = 0; k < HH; k++) {
        float4 b4 = *(const float4*)(wb + (size_t)k * NP);
        float2 b0 = make_float2(b4.x, b4.y), b1 = make_float2(b4.z, b4.w);
#pragma unroll
        for (int i = 0; i < 8; i++) {
            float a = __ldg(xr + i * 8 * HH + k);   // warp-uniform broadcast
            float2 a2 = make_float2(a, a);
            acc[i][0] = fma2(acc[i][0], a2, b0);
            acc[i][1] = fma2(acc[i][1], a2, b1);
        }
    }

    float* xg = (l == 0) ? g_xg0 : g_xg1;
    float4 bias = *(const float4*)(g_bsum + l * NP + nt * 128 + 4 * lane);
    if (nt < 4 || lane < 28) {
#pragma unroll
        for (int i = 0; i < 8; i++) {
            int m = m0 + wp + 8 * i;
            int b = m >> 7, t = m & 127;            // m = b*T + t
            size_t rb = ((size_t)t * BB + b) * G4 + nt * 128 + 4 * lane;
            float4 v = make_float4(acc[i][0].x + bias.x, acc[i][0].y + bias.y,
                                   acc[i][1].x + bias.z, acc[i][1].y + bias.w);
            *(float4*)(xg + rb) = v;
        }
    }
}

// ---------------- kernel 2: full recurrence ----------------
constexpr int ADJ_F = HH * 160;                 // 24960 floats
constexpr int BUF_F = 64 * HH;                  // 9984 floats
constexpr int RSMEM = (ADJ_F + 3 * BUF_F) * 4;  // 219,648 B

__global__ __launch_bounds__(512, 1) void recur2(
        const float* __restrict__ gw1, const float* __restrict__ gw2,
        float* __restrict__ out) {
    extern __shared__ float sm[];
    float* sadjt = sm;                 // [k][160] (o contiguous)
    float* bufs  = sm + ADJ_F;
    const int l = blockIdx.y;
    const int r0 = blockIdx.x * 64;
    const int tid = threadIdx.x, lane = tid & 31, wp = tid >> 5;  // wp 0..15

    for (int i = tid; i < ADJ_F / 4; i += 512)
        ((float4*)sadjt)[i] = ((const float4*)g_adjt)[i];
    for (int i = tid; i < 3 * BUF_F; i += 512) bufs[i] = 0.f;
    __syncthreads();

    float* sh  = bufs;                // h (swaps with stp)
    float* scc = bufs + BUF_F;        // c (in place)
    float* stp = bufs + 2 * BUF_F;    // temp / next h

    const float c1 = gw1[l], c2 = gw2[l];
    const float* xg = (l == 0) ? g_xg0 : g_xg1;
    const float4* __restrict__ wb = g_wp4 + (size_t)l * HH * 192;

    // GCN half-step: OUT[m][o] = act( w * sum_k IN[m][k]*adjT[k][o] )
    auto gcnp = [&](const float* IN, float* OUT, float w, bool rl) {
        float2 acc[4][3];
#pragma unroll
        for (int i = 0; i < 4; i++)
#pragma unroll
            for (int j = 0; j < 3; j++) acc[i][j] = make_float2(0.f, 0.f);
#pragma unroll 2
        for (int k = 0; k < HH; k++) {
            const float* ar = sadjt + k * 160 + 2 * lane;
            float2 b0 = *(const float2*)(ar);
            float2 b1 = *(const float2*)(ar + 64);
            float2 b2 = *(const float2*)(ar + 128);
#pragma unroll
            for (int i = 0; i < 4; i++) {
                float a = IN[(wp + 16 * i) * HH + k];   // broadcast
                float2 a2 = make_float2(a, a);
                acc[i][0] = fma2(acc[i][0], a2, b0);
                acc[i][1] = fma2(acc[i][1], a2, b1);
                acc[i][2] = fma2(acc[i][2], a2, b2);
            }
        }
#pragma unroll
        for (int j = 0; j < 3; j++) {
            int o0 = 2 * lane + 64 * j;
            if (o0 < HH) {
#pragma unroll
                for (int i = 0; i < 4; i++) {
                    float vx = w * acc[i][j].x, vy = w * acc[i][j].y;
                    float2 v;
                    if (rl) { v.x = fmaxf(vx, 0.f); v.y = fmaxf(vy, 0.f); }
                    else    { v.x = sigmoidf_(vx);  v.y = sigmoidf_(vy); }
                    *(float2*)(OUT + (wp + 16 * i) * HH + o0) = v;
                }
            }
        }
    };

    auto gates = [&](int t) {
#pragma unroll 1
        for (int j = 0; j < 3; ++j) {
            const int op = lane + 32 * j;            // o-pair index
            float2 acc[4][4];
#pragma unroll
            for (int i = 0; i < 4; i++)
#pragma unroll
                for (int g = 0; g < 4; g++) acc[i][g] = make_float2(0.f, 0.f);
#pragma unroll 2
            for (int k = 0; k < HH; ++k) {
                float4 v0 = __ldg(&wb[(k * 2 + 0) * 96 + op]);   // gates i,f
                float4 v1 = __ldg(&wb[(k * 2 + 1) * 96 + op]);   // gates c,o
                float2 wi = make_float2(v0.x, v0.y), wf = make_float2(v0.z, v0.w);
                float2 wc = make_float2(v1.x, v1.y), wo = make_float2(v1.z, v1.w);
#pragma unroll
                for (int i = 0; i < 4; i++) {
                    float a = sh[(wp + 16 * i) * HH + k];        // broadcast
                    float2 a2 = make_float2(a, a);
                    acc[i][0] = fma2(acc[i][0], a2, wi);
                    acc[i][1] = fma2(acc[i][1], a2, wf);
                    acc[i][2] = fma2(acc[i][2], a2, wc);
                    acc[i][3] = fma2(acc[i][3], a2, wo);
                }
            }
            const int o0 = 2 * op;
            if (o0 < HH) {
#pragma unroll
                for (int i = 0; i < 4; i++) {
                    int m = wp + 16 * i;
                    int row = r0 + m;
                    size_t xb = ((size_t)t * BB + row) * G4;
                    float2 xi = *(const float2*)(xg + xb + o0);
                    float2 xf = *(const float2*)(xg + xb + HH + o0);
                    float2 xc = *(const float2*)(xg + xb + 2 * HH + o0);
                    float2 xo = *(const float2*)(xg + xb + 3 * HH + o0);
                    float2 cold = *(const float2*)(scc + m * HH + o0);
                    float2 ct, hn;
                    {
                        float it = sigmoidf_(acc[i][0].x + xi.x);
                        float ft = sigmoidf_(acc[i][1].x + xf.x);
                        float cb = tanhf_fast(acc[i][2].x + xc.x);
                        float ot = sigmoidf_(acc[i][3].x + xo.x);
                        ct.x = ft * cold.x + it * cb;
                        hn.x = ot * tanhf_fast(ct.x);
                    }
                    {
                        float it = sigmoidf_(acc[i][0].y + xi.y);
                        float ft = sigmoidf_(acc[i][1].y + xf.y);
                        float cb = tanhf_fast(acc[i][2].y + xc.y);
                        float ot = sigmoidf_(acc[i][3].y + xo.y);
                        ct.y = ft * cold.y + it * cb;
                        hn.y = ot * tanhf_fast(ct.y);
                    }
                    *(float2*)(scc + m * HH + o0) = ct;
                    *(float2*)(stp + m * HH + o0) = hn;
                    if (l == 1)
                        *(float2*)(g_ys + ((size_t)row * TT + t) * HH + o0) = hn;
                }
            }
        }
    };

    for (int t = 0; t < TT; ++t) {
        if (t > 0) {
            gcnp(sh,  stp, c1, true);  __syncthreads();
            gcnp(stp, sh,  c2, false); __syncthreads();   // sh = gcn(h)
            gcnp(scc, stp, c1, true);  __syncthreads();
            gcnp(stp, scc, c2, false); __syncthreads();   // scc = gcn(c)
        }
        gates(t);
        __syncthreads();
        float* tsw = sh; sh = stp; stp = tsw;
    }

    constexpr size_t OUT0 = (size_t)BB * OO * HH;
    constexpr size_t HN   = (size_t)LL * BB * HH;
    for (int i = tid; i < 64 * HH; i += 512) {
        int m = i / HH, o = i - m * HH;
        int row = r0 + m;
        size_t off = ((size_t)l * BB + row) * HH + o;
        out[OUT0 + off]      = sh[m * HH + o];
        out[OUT0 + HN + off] = scc[m * HH + o];
    }
}

// ---------------- kernel 3: output projection ----------------
constexpr int YROW = TT * HH;  // 19968
constexpr int OSMEM = (YROW + OO * TT + OO) * 4;

__global__ __launch_bounds__(256) void out_kernel(const float* __restrict__ Wout,
                                                  const float* __restrict__ bout,
                                                  float* __restrict__ out) {
    extern __shared__ float sm[];
    float* sy = sm;
    float* sw = sm + YROW;
    float* sb = sw + OO * TT;
    const int b = blockIdx.x;
    const int tid = threadIdx.x;
    const float* yb = g_ys + (size_t)b * YROW;
    for (int i = tid; i < YROW / 4; i += 256) ((float4*)sy)[i] = ((const float4*)yb)[i];
    for (int i = tid; i < OO * TT; i += 256) sw[i] = Wout[i];
    if (tid < OO) sb[tid] = bout[tid];
    __syncthreads();
    for (int idx = tid; idx < HH * OO; idx += 256) {
        int f = idx / OO, jj = idx - f * OO;
        const float* yr = sy + f * TT;
        const float* wr = sw + jj * TT;
        float2 a = make_float2(0.f, 0.f);
#pragma unroll 4
        for (int p = 0; p < TT / 2; ++p)
            a = fma2(a, *(const float2*)(yr + 2 * p), *(const float2*)(wr + 2 * p));
        out[(size_t)b * (HH * OO) + idx] = a.x + a.y + sb[jj];
    }
}

// ---------------- launcher ----------------
extern "C" void kernel_launch(void* const* d_in, const int* in_sizes, int n_in,
                              void* d_out, int out_size) {
    const float* x   = (const float*)d_in[0];
    const float* adj = (const float*)d_in[1];

    XArgs xa;
    xa.W[0] = (const float*)d_in[2];  xa.bx[0] = (const float*)d_in[3];
    xa.W[1] = (const float*)d_in[6];  xa.bx[1] = (const float*)d_in[7];
    xa.W[2] = (const float*)d_in[10]; xa.bx[2] = (const float*)d_in[11];
    xa.W[3] = (const float*)d_in[14]; xa.bx[3] = (const float*)d_in[15];
    xa.bh[0] = (const float*)d_in[5];
    xa.bh[1] = (const float*)d_in[9];
    xa.bh[2] = (const float*)d_in[13];
    xa.bh[3] = (const float*)d_in[17];

    HArgs ha;
    ha.W[0] = (const float*)d_in[4];
    ha.W[1] = (const float*)d_in[8];
    ha.W[2] = (const float*)d_in[12];
    ha.W[3] = (const float*)d_in[16];

    const float* gw1  = (const float*)d_in[18];
    const float* gw2  = (const float*)d_in[19];
    const float* Wout = (const float*)d_in[20];
    const float* bout = (const float*)d_in[21];
    float* out = (float*)d_out;

    cudaFuncSetAttribute(recur2,     cudaFuncAttributeMaxDynamicSharedMemorySize, RSMEM);
    cudaFuncSetAttribute(out_kernel, cudaFuncAttributeMaxDynamicSharedMemorySize, OSMEM);

    setup_wxt <<<(LL * HH * NP + 255) / 256, 256>>>(xa);
    setup_bsum<<<(LL * NP + 255) / 256, 256>>>(xa);
    setup_adjt<<<(HH * 160 + 255) / 256, 256>>>(adj);
    setup_wp4 <<<(LL * HH * 192 + 255) / 256, 256>>>(ha);

    dim3 pg(BB * TT / 64, 5, LL);            // 8192 x 5 x 2
    prelude2<<<pg, 256>>>(x);

    dim3 rg(BB / 64, LL);                    // 64 x 2 = 128 persistent blocks
    recur2<<<rg, 512, RSMEM>>>(gw1, gw2, out);

    out_kernel<<<BB, 256, OSMEM>>>(Wout, bout, out);
}

// round 7
// speedup vs baseline: 3.8758x; 1.6077x over previous
#include <cuda_runtime.h>
#include <cuda_bf16.h>
#include <cstddef>
#include <cstdint>

// Problem dims
constexpr int BB = 4096;   // batch
constexpr int TT = 128;    // time
constexpr int HH = 156;    // hidden/nodes
constexpr int LL = 2;      // layers
constexpr int OO = 12;     // output len
constexpr int G4 = 4 * HH; // 624  (gate cols, ordered n' = 4*o + g; g: 0=i,1=f,2=c,3=o)
constexpr int NP = 640;    // padded gate width

// Scratch (device globals)
constexpr size_t XG_ELEMS = (size_t)TT * BB * G4;      // ~1.22 GiB each
__device__ float g_xg0[XG_ELEMS];
__device__ float g_xg1[XG_ELEMS];
__device__ float g_ys[(size_t)BB * TT * HH];           // ~312 MiB

// Preprocessed data
__device__ float g_wxt[LL * HH * NP];    // x-weights transposed: [l][k][n'(640)]
__device__ float g_bsum[LL * NP];        // bx+bh in n' order
// mma B-fragment packs: uint4 = {b0_hi, b1_hi, b0_lo, b1_lo} per (n-tile, k-step, lane)
__device__ uint4 g_adjf[20 * 10 * 32];        // adj^T fragments   (~100 KB)
__device__ uint4 g_wf[LL * 80 * 10 * 32];     // gate-weight frags (~819 KB)

// ---------------- generic helpers ----------------
__device__ __forceinline__ float2 fma2(float2 d, float2 a, float2 b) {
    unsigned long long dd = *reinterpret_cast<unsigned long long*>(&d);
    unsigned long long aa = *reinterpret_cast<unsigned long long*>(&a);
    unsigned long long bb = *reinterpret_cast<unsigned long long*>(&b);
    asm("fma.rn.f32x2 %0, %1, %2, %0;" : "+l"(dd) : "l"(aa), "l"(bb));
    return *reinterpret_cast<float2*>(&dd);
}
__device__ __forceinline__ float sigmoidf_(float x) {
    return __fdividef(1.0f, 1.0f + __expf(-x));
}
__device__ __forceinline__ float tanhf_fast(float x) {
    float ax = fabsf(x);
    float e = __expf(-2.0f * ax);
    float t = __fdividef(1.0f - e, 1.0f + e);
    return copysignf(t, x);
}
__device__ __forceinline__ uint32_t smem_u32(const void* p) {
    uint32_t a;
    asm("{ .reg .u64 t; cvta.to.shared.u64 t, %1; cvt.u32.u64 %0, t; }" : "=r"(a) : "l"(p));
    return a;
}
// split (x,y) into packed bf16 hi / bf16 lo residual pairs
__device__ __forceinline__ uint2 split2(float x, float y) {
    __nv_bfloat16 hx = __float2bfloat16(x);
    __nv_bfloat16 hy = __float2bfloat16(y);
    __nv_bfloat16 lx = __float2bfloat16(x - __bfloat162float(hx));
    __nv_bfloat16 ly = __float2bfloat16(y - __bfloat162float(hy));
    uint2 r;
    r.x = (uint32_t)*reinterpret_cast<uint16_t*>(&hx) | ((uint32_t)*reinterpret_cast<uint16_t*>(&hy) << 16);
    r.y = (uint32_t)*reinterpret_cast<uint16_t*>(&lx) | ((uint32_t)*reinterpret_cast<uint16_t*>(&ly) << 16);
    return r;
}
__device__ __forceinline__ void ldm_x4(uint32_t* r, uint32_t addr) {
    asm volatile("ldmatrix.sync.aligned.m8n8.x4.shared.b16 {%0,%1,%2,%3}, [%4];"
                 : "=r"(r[0]), "=r"(r[1]), "=r"(r[2]), "=r"(r[3]) : "r"(addr));
}
__device__ __forceinline__ void mma_bf16(float* c, const uint32_t* a, uint32_t b0, uint32_t b1) {
    asm volatile(
        "mma.sync.aligned.m16n8k16.row.col.f32.bf16.bf16.f32 "
        "{%0,%1,%2,%3}, {%4,%5,%6,%7}, {%8,%9}, {%0,%1,%2,%3};"
        : "+f"(c[0]), "+f"(c[1]), "+f"(c[2]), "+f"(c[3])
        : "r"(a[0]), "r"(a[1]), "r"(a[2]), "r"(a[3]), "r"(b0), "r"(b1));
}

struct XArgs {
    const float* W[4];   // Wix, Wfx, Wcx, Wox   each [L,H,H]
    const float* bx[4];
    const float* bh[4];
};
struct HArgs {
    const float* W[4];   // Wih, Wfh, Wch, Woh  each [L,H,H]
};

// ---------------- setup kernels ----------------
__global__ __launch_bounds__(256) void setup_wxt(XArgs A) {
    int idx = blockIdx.x * 256 + threadIdx.x;
    if (idx >= LL * HH * NP) return;
    int n = idx % NP, k = (idx / NP) % HH, l = idx / (NP * HH);
    int o = n >> 2, g = n & 3;
    g_wxt[idx] = (o < HH) ? A.W[g][((size_t)l * HH + o) * HH + k] : 0.f;
}
__global__ __launch_bounds__(256) void setup_bsum(XArgs A) {
    int idx = blockIdx.x * 256 + threadIdx.x;
    if (idx >= LL * NP) return;
    int n = idx % NP, l = idx / NP;
    int o = n >> 2, g = n & 3;
    g_bsum[idx] = (o < HH) ? (A.bx[g][l * HH + o] + A.bh[g][l * HH + o]) : 0.f;
}
__global__ __launch_bounds__(256) void setup_adjf(const float* __restrict__ adj) {
    int idx = blockIdx.x * 256 + threadIdx.x;
    if (idx >= 20 * 10 * 32) return;
    int lane = idx & 31, r = idx >> 5;
    int ks = r % 10, nt = r / 10;
    int gid = lane >> 2, tg = lane & 3;
    int n = nt * 8 + gid;           // output node
    int k0 = ks * 16 + 2 * tg;
    auto val = [&](int k) -> float { return (n < HH && k < HH) ? adj[n * HH + k] : 0.f; };
    uint2 b0 = split2(val(k0), val(k0 + 1));
    uint2 b1 = split2(val(k0 + 8), val(k0 + 9));
    g_adjf[idx] = make_uint4(b0.x, b1.x, b0.y, b1.y);
}
__global__ __launch_bounds__(256) void setup_wf(HArgs A) {
    int idx = blockIdx.x * 256 + threadIdx.x;
    if (idx >= LL * 80 * 10 * 32) return;
    int lane = idx & 31, r = idx >> 5;
    int ks = r % 10; r /= 10;
    int nt = r % 80;
    int l  = r / 80;
    int gid = lane >> 2, tg = lane & 3;
    int np = nt * 8 + gid;          // n' = 4*o + g
    int o = np >> 2, g = np & 3;
    int k0 = ks * 16 + 2 * tg;
    auto val = [&](int k) -> float {
        return (o < HH && k < HH) ? A.W[g][((size_t)l * HH + o) * HH + k] : 0.f;
    };
    uint2 b0 = split2(val(k0), val(k0 + 1));
    uint2 b1 = split2(val(k0 + 8), val(k0 + 9));
    g_wf[idx] = make_uint4(b0.x, b1.x, b0.y, b1.y);
}

// ---------------- kernel 1: prelude XG = x @ Wcat_x^T + (bx+bh)  (fp32, proven) ----------------
__global__ __launch_bounds__(256) void prelude2(const float* __restrict__ x) {
    const int l = blockIdx.z, nt = blockIdx.y;
    const int m0 = blockIdx.x * 64;
    const int lane = threadIdx.x & 31, wp = threadIdx.x >> 5;   // 8 warps
    const float* __restrict__ wb = g_wxt + (size_t)l * HH * NP + nt * 128 + 4 * lane;
    const float* __restrict__ xr = x + (size_t)(m0 + wp) * HH;

    float2 acc[8][2];
#pragma unroll
    for (int i = 0; i < 8; i++) { acc[i][0] = make_float2(0.f, 0.f); acc[i][1] = make_float2(0.f, 0.f); }

#pragma unroll 2
    for (int k = 0; k < HH; k++) {
        float4 b4 = *(const float4*)(wb + (size_t)k * NP);
        float2 b0 = make_float2(b4.x, b4.y), b1 = make_float2(b4.z, b4.w);
#pragma unroll
        for (int i = 0; i < 8; i++) {
            float a = __ldg(xr + i * 8 * HH + k);
            float2 a2 = make_float2(a, a);
            acc[i][0] = fma2(acc[i][0], a2, b0);
            acc[i][1] = fma2(acc[i][1], a2, b1);
        }
    }

    float* xg = (l == 0) ? g_xg0 : g_xg1;
    float4 bias = *(const float4*)(g_bsum + l * NP + nt * 128 + 4 * lane);
    if (nt < 4 || lane < 28) {
#pragma unroll
        for (int i = 0; i < 8; i++) {
            int m = m0 + wp + 8 * i;
            int b = m >> 7, t = m & 127;            // m = b*T + t
            size_t rb = ((size_t)t * BB + b) * G4 + nt * 128 + 4 * lane;
            float4 v = make_float4(acc[i][0].x + bias.x, acc[i][0].y + bias.y,
                                   acc[i][1].x + bias.z, acc[i][1].y + bias.w);
            *(float4*)(xg + rb) = v;
        }
    }
}

// ---------------- kernel 2: full recurrence via mma.sync bf16x3 ----------------
constexpr int SROWB = 336;                 // image row stride in bytes (168 bf16)
constexpr int IMG = 64 * SROWB;            // 21504 B per image
constexpr int RSMEM2 = 6 * IMG;            // 129024 B

__global__ __launch_bounds__(320, 1) void recur_mma(
        const float* __restrict__ gw1, const float* __restrict__ gw2,
        float* __restrict__ out) {
    extern __shared__ char smem[];
    const uint32_t smb = smem_u32(smem);
    const int l = blockIdx.y;
    const int r0 = blockIdx.x * 64;
    const int tid = threadIdx.x, lane = tid & 31, wid = tid >> 5;  // 10 warps
    const int gid = lane >> 2, tg = lane & 3;
    const bool evenl = ((lane & 1) == 0);
    const uint32_t loff = (uint32_t)(((lane & 7) + 8 * ((lane >> 3) & 1)) * SROWB + (lane >> 4) * 16);

    for (int i = tid; i < RSMEM2 / 4; i += 320) ((uint32_t*)smem)[i] = 0u;
    __syncthreads();

    uint32_t hH = 0, hL = IMG, cH = 2 * IMG, cL = 3 * IMG, tH = 4 * IMG, tL = 5 * IMG;

    const float c1 = gw1[l], c2 = gw2[l];
    const float* __restrict__ xg = (l == 0) ? g_xg0 : g_xg1;
    const uint4* __restrict__ wf = g_wf + (size_t)l * 80 * 10 * 32;

    // one GCN half-step: OUT[m][o] = act( w * sum_k IN[m][k] * adj[o][k] )
    auto gcn = [&](uint32_t inH, uint32_t inL, uint32_t outH, uint32_t outL, float w, bool rl) {
        float acc[2][4][4];
#pragma unroll
        for (int j = 0; j < 2; j++)
#pragma unroll
            for (int m = 0; m < 4; m++)
#pragma unroll
                for (int q = 0; q < 4; q++) acc[j][m][q] = 0.f;
#pragma unroll 1
        for (int ks = 0; ks < 10; ++ks) {
            uint32_t Ah[4][4], Al[4][4];
#pragma unroll
            for (int m = 0; m < 4; m++) {
                ldm_x4(Ah[m], smb + inH + (uint32_t)(m * 16 * SROWB + ks * 32) + loff);
                ldm_x4(Al[m], smb + inL + (uint32_t)(m * 16 * SROWB + ks * 32) + loff);
            }
#pragma unroll
            for (int j = 0; j < 2; j++) {
                uint4 B = g_adjf[((size_t)(wid + 10 * j) * 10 + ks) * 32 + lane];
#pragma unroll
                for (int m = 0; m < 4; m++) {
                    mma_bf16(acc[j][m], Ah[m], B.x, B.y);
                    mma_bf16(acc[j][m], Al[m], B.x, B.y);
                    mma_bf16(acc[j][m], Ah[m], B.z, B.w);
                }
            }
        }
#pragma unroll
        for (int j = 0; j < 2; j++) {
            int colByte = ((wid + 10 * j) * 8 + 2 * tg) * 2;
#pragma unroll
            for (int m = 0; m < 4; m++) {
                float v0 = w * acc[j][m][0], v1 = w * acc[j][m][1];
                float v2 = w * acc[j][m][2], v3 = w * acc[j][m][3];
                if (rl) {
                    v0 = fmaxf(v0, 0.f); v1 = fmaxf(v1, 0.f);
                    v2 = fmaxf(v2, 0.f); v3 = fmaxf(v3, 0.f);
                } else {
                    v0 = sigmoidf_(v0); v1 = sigmoidf_(v1);
                    v2 = sigmoidf_(v2); v3 = sigmoidf_(v3);
                }
                uint2 p01 = split2(v0, v1);
                uint2 p23 = split2(v2, v3);
                int rb0 = (m * 16 + gid) * SROWB + colByte;
                int rb1 = rb0 + 8 * SROWB;
                *(uint32_t*)(smem + outH + rb0) = p01.x;
                *(uint32_t*)(smem + outL + rb0) = p01.y;
                *(uint32_t*)(smem + outH + rb1) = p23.x;
                *(uint32_t*)(smem + outL + rb1) = p23.y;
            }
        }
    };

    // gates: preacts = h @ W^T (n' = 4o+g cols) + xg; LSTM cell update in-register
    auto gates = [&](int t) {
#pragma unroll 1
        for (int jp = 0; jp < 4; ++jp) {
            float acc[2][4][4];
#pragma unroll
            for (int j = 0; j < 2; j++)
#pragma unroll
                for (int m = 0; m < 4; m++)
#pragma unroll
                    for (int q = 0; q < 4; q++) acc[j][m][q] = 0.f;
#pragma unroll 1
            for (int ks = 0; ks < 10; ++ks) {
                uint32_t Ah[4][4], Al[4][4];
#pragma unroll
                for (int m = 0; m < 4; m++) {
                    ldm_x4(Ah[m], smb + hH + (uint32_t)(m * 16 * SROWB + ks * 32) + loff);
                    ldm_x4(Al[m], smb + hL + (uint32_t)(m * 16 * SROWB + ks * 32) + loff);
                }
#pragma unroll
                for (int j = 0; j < 2; j++) {
                    int nt = wid + 10 * j + 20 * jp;
                    uint4 B = wf[((size_t)nt * 10 + ks) * 32 + lane];
#pragma unroll
                    for (int m = 0; m < 4; m++) {
                        mma_bf16(acc[j][m], Ah[m], B.x, B.y);
                        mma_bf16(acc[j][m], Al[m], B.x, B.y);
                        mma_bf16(acc[j][m], Ah[m], B.z, B.w);
                    }
                }
            }
#pragma unroll
            for (int j = 0; j < 2; j++) {
                int nt = wid + 10 * j + 20 * jp;
                int o = 2 * nt + (tg >> 1);
#pragma unroll
                for (int m = 0; m < 4; m++) {
                    float a0 = acc[j][m][0], a1 = acc[j][m][1];
                    float a2 = acc[j][m][2], a3 = acc[j][m][3];
                    float e0 = __shfl_xor_sync(0xffffffffu, a0, 1);
                    float e1 = __shfl_xor_sync(0xffffffffu, a1, 1);
                    float e2 = __shfl_xor_sync(0xffffffffu, a2, 1);
                    float e3 = __shfl_xor_sync(0xffffffffu, a3, 1);
                    if (o < HH) {
                        int row = m * 16 + gid + (evenl ? 0 : 8);
                        float pi = evenl ? a0 : e2;
                        float pf = evenl ? a1 : e3;
                        float pc = evenl ? e0 : a2;
                        float po = evenl ? e1 : a3;
                        int grow = r0 + row;
                        const float4 xv = *(const float4*)(xg + ((size_t)t * BB + grow) * G4 + 4 * o);
                        float it = sigmoidf_(pi + xv.x);
                        float ft = sigmoidf_(pf + xv.y);
                        float cb = tanhf_fast(pc + xv.z);
                        float ot = sigmoidf_(po + xv.w);
                        int sb = row * SROWB + 2 * o;
                        float cold = __bfloat162float(*(__nv_bfloat16*)(smem + cH + sb))
                                   + __bfloat162float(*(__nv_bfloat16*)(smem + cL + sb));
                        float ct = ft * cold + it * cb;
                        float hn = ot * tanhf_fast(ct);
                        __nv_bfloat16 cth = __float2bfloat16(ct);
                        *(__nv_bfloat16*)(smem + cH + sb) = cth;
                        *(__nv_bfloat16*)(smem + cL + sb) = __float2bfloat16(ct - __bfloat162float(cth));
                        __nv_bfloat16 hnh = __float2bfloat16(hn);
                        *(__nv_bfloat16*)(smem + tH + sb) = hnh;
                        *(__nv_bfloat16*)(smem + tL + sb) = __float2bfloat16(hn - __bfloat162float(hnh));
                        if (l == 1) g_ys[((size_t)grow * TT + t) * HH + o] = hn;
                    }
                }
            }
        }
    };

    for (int t = 0; t < TT; ++t) {
        if (t > 0) {
            gcn(hH, hL, tH, tL, c1, true);  __syncthreads();
            gcn(tH, tL, hH, hL, c2, false); __syncthreads();   // H = gcn(h)
            gcn(cH, cL, tH, tL, c1, true);  __syncthreads();
            gcn(tH, tL, cH, cL, c2, false); __syncthreads();   // C = gcn(c)
        }
        gates(t);                      // reads H (A) + C (cold); writes C (ct), T (new h)
        __syncthreads();
        uint32_t s;
        s = hH; hH = tH; tH = s;
        s = hL; hL = tL; tL = s;
    }

    // final states -> h_n, c_n
    constexpr size_t OUT0 = (size_t)BB * OO * HH;
    constexpr size_t HN   = (size_t)LL * BB * HH;
    for (int i = tid; i < 64 * HH; i += 320) {
        int m = i / HH, o = i - m * HH;
        int sb = m * SROWB + 2 * o;
        float hv = __bfloat162float(*(__nv_bfloat16*)(smem + hH + sb))
                 + __bfloat162float(*(__nv_bfloat16*)(smem + hL + sb));
        float cv = __bfloat162float(*(__nv_bfloat16*)(smem + cH + sb))
                 + __bfloat162float(*(__nv_bfloat16*)(smem + cL + sb));
        size_t off = ((size_t)l * BB + (r0 + m)) * HH + o;
        out[OUT0 + off]      = hv;
        out[OUT0 + HN + off] = cv;
    }
}

// ---------------- kernel 3: output projection ----------------
constexpr int YROW = TT * HH;  // 19968
constexpr int OSMEM = (YROW + OO * TT + OO) * 4;

__global__ __launch_bounds__(256) void out_kernel(const float* __restrict__ Wout,
                                                  const float* __restrict__ bout,
                                                  float* __restrict__ out) {
    extern __shared__ float sm[];
    float* sy = sm;
    float* sw = sm + YROW;
    float* sb = sw + OO * TT;
    const int b = blockIdx.x;
    const int tid = threadIdx.x;
    const float* yb = g_ys + (size_t)b * YROW;
    for (int i = tid; i < YROW / 4; i += 256) ((float4*)sy)[i] = ((const float4*)yb)[i];
    for (int i = tid; i < OO * TT; i += 256) sw[i] = Wout[i];
    if (tid < OO) sb[tid] = bout[tid];
    __syncthreads();
    for (int idx = tid; idx < HH * OO; idx += 256) {
        int f = idx / OO, jj = idx - f * OO;
        const float* yr = sy + f * TT;
        const float* wr = sw + jj * TT;
        float2 a = make_float2(0.f, 0.f);
#pragma unroll 4
        for (int p = 0; p < TT / 2; ++p)
            a = fma2(a, *(const float2*)(yr + 2 * p), *(const float2*)(wr + 2 * p));
        out[(size_t)b * (HH * OO) + idx] = a.x + a.y + sb[jj];
    }
}

// ---------------- launcher ----------------
extern "C" void kernel_launch(void* const* d_in, const int* in_sizes, int n_in,
                              void* d_out, int out_size) {
    const float* x   = (const float*)d_in[0];
    const float* adj = (const float*)d_in[1];

    XArgs xa;
    xa.W[0] = (const float*)d_in[2];  xa.bx[0] = (const float*)d_in[3];
    xa.W[1] = (const float*)d_in[6];  xa.bx[1] = (const float*)d_in[7];
    xa.W[2] = (const float*)d_in[10]; xa.bx[2] = (const float*)d_in[11];
    xa.W[3] = (const float*)d_in[14]; xa.bx[3] = (const float*)d_in[15];
    xa.bh[0] = (const float*)d_in[5];
    xa.bh[1] = (const float*)d_in[9];
    xa.bh[2] = (const float*)d_in[13];
    xa.bh[3] = (const float*)d_in[17];

    HArgs ha;
    ha.W[0] = (const float*)d_in[4];
    ha.W[1] = (const float*)d_in[8];
    ha.W[2] = (const float*)d_in[12];
    ha.W[3] = (const float*)d_in[16];

    const float* gw1  = (const float*)d_in[18];
    const float* gw2  = (const float*)d_in[19];
    const float* Wout = (const float*)d_in[20];
    const float* bout = (const float*)d_in[21];
    float* out = (float*)d_out;

    cudaFuncSetAttribute(recur_mma,  cudaFuncAttributeMaxDynamicSharedMemorySize, RSMEM2);
    cudaFuncSetAttribute(out_kernel, cudaFuncAttributeMaxDynamicSharedMemorySize, OSMEM);

    setup_wxt <<<(LL * HH * NP + 255) / 256, 256>>>(xa);
    setup_bsum<<<(LL * NP + 255) / 256, 256>>>(xa);
    setup_adjf<<<(20 * 10 * 32 + 255) / 256, 256>>>(adj);
    setup_wf  <<<(LL * 80 * 10 * 32 + 255) / 256, 256>>>(ha);

    dim3 pg(BB * TT / 64, 5, LL);            // 8192 x 5 x 2
    prelude2<<<pg, 256>>>(x);

    dim3 rg(BB / 64, LL);                    // 64 x 2 = 128 blocks
    recur_mma<<<rg, 320, RSMEM2>>>(gw1, gw2, out);

    out_kernel<<<BB, 256, OSMEM>>>(Wout, bout, out);
}

// round 8
// speedup vs baseline: 3.8883x; 1.0032x over previous
#include <cuda_runtime.h>
#include <cuda_bf16.h>
#include <cstddef>
#include <cstdint>

// Problem dims
constexpr int BB = 4096;   // batch
constexpr int TT = 128;    // time
constexpr int HH = 156;    // hidden/nodes
constexpr int LL = 2;      // layers
constexpr int OO = 12;     // output len
constexpr int G4 = 4 * HH; // 624  (gate cols, ordered n' = 4*o + g; g: 0=i,1=f,2=c,3=o)
constexpr int NP = 640;    // padded gate width

// Scratch (device globals)
constexpr size_t XG_ELEMS = (size_t)TT * BB * G4;      // ~1.22 GiB each
__device__ float g_xg0[XG_ELEMS];
__device__ float g_xg1[XG_ELEMS];
__device__ float g_ys[(size_t)BB * TT * HH];           // ~312 MiB

// Preprocessed data
__device__ float g_wxt[LL * HH * NP];    // x-weights transposed: [l][k][n'(640)]
__device__ float g_bsum[LL * NP];        // bx+bh in n' order
// mma B-fragment packs: uint4 = {b0_hi, b1_hi, b0_lo, b1_lo} per (n-tile, k-step, lane)
__device__ uint4 g_adjf[20 * 10 * 32];        // adj^T fragments   (~100 KB)
__device__ uint4 g_wf[LL * 80 * 10 * 32];     // gate-weight frags (~819 KB)

// ---------------- generic helpers ----------------
__device__ __forceinline__ float2 fma2(float2 d, float2 a, float2 b) {
    unsigned long long dd = *reinterpret_cast<unsigned long long*>(&d);
    unsigned long long aa = *reinterpret_cast<unsigned long long*>(&a);
    unsigned long long bb = *reinterpret_cast<unsigned long long*>(&b);
    asm("fma.rn.f32x2 %0, %1, %2, %0;" : "+l"(dd) : "l"(aa), "l"(bb));
    return *reinterpret_cast<float2*>(&dd);
}
__device__ __forceinline__ float sigmoidf_(float x) {
    return __fdividef(1.0f, 1.0f + __expf(-x));
}
__device__ __forceinline__ float tanhf_fast(float x) {
    float ax = fabsf(x);
    float e = __expf(-2.0f * ax);
    float t = __fdividef(1.0f - e, 1.0f + e);
    return copysignf(t, x);
}
__device__ __forceinline__ uint32_t smem_u32(const void* p) {
    uint32_t a;
    asm("{ .reg .u64 t; cvta.to.shared.u64 t, %1; cvt.u32.u64 %0, t; }" : "=r"(a) : "l"(p));
    return a;
}
// split (x,y) into packed bf16 hi / bf16 lo residual pairs
__device__ __forceinline__ uint2 split2(float x, float y) {
    __nv_bfloat16 hx = __float2bfloat16(x);
    __nv_bfloat16 hy = __float2bfloat16(y);
    __nv_bfloat16 lx = __float2bfloat16(x - __bfloat162float(hx));
    __nv_bfloat16 ly = __float2bfloat16(y - __bfloat162float(hy));
    uint2 r;
    r.x = (uint32_t)*reinterpret_cast<uint16_t*>(&hx) | ((uint32_t)*reinterpret_cast<uint16_t*>(&hy) << 16);
    r.y = (uint32_t)*reinterpret_cast<uint16_t*>(&lx) | ((uint32_t)*reinterpret_cast<uint16_t*>(&ly) << 16);
    return r;
}
__device__ __forceinline__ void ldm_x4(uint32_t* r, uint32_t addr) {
    asm volatile("ldmatrix.sync.aligned.m8n8.x4.shared.b16 {%0,%1,%2,%3}, [%4];"
                 : "=r"(r[0]), "=r"(r[1]), "=r"(r[2]), "=r"(r[3]) : "r"(addr));
}
__device__ __forceinline__ void mma_bf16(float* c, const uint32_t* a, uint32_t b0, uint32_t b1) {
    asm volatile(
        "mma.sync.aligned.m16n8k16.row.col.f32.bf16.bf16.f32 "
        "{%0,%1,%2,%3}, {%4,%5,%6,%7}, {%8,%9}, {%0,%1,%2,%3};"
        : "+f"(c[0]), "+f"(c[1]), "+f"(c[2]), "+f"(c[3])
        : "r"(a[0]), "r"(a[1]), "r"(a[2]), "r"(a[3]), "r"(b0), "r"(b1));
}

struct XArgs {
    const float* W[4];   // Wix, Wfx, Wcx, Wox   each [L,H,H]
    const float* bx[4];
    const float* bh[4];
};
struct HArgs {
    const float* W[4];   // Wih, Wfh, Wch, Woh  each [L,H,H]
};

// ---------------- setup kernels ----------------
__global__ __launch_bounds__(256) void setup_wxt(XArgs A) {
    int idx = blockIdx.x * 256 + threadIdx.x;
    if (idx >= LL * HH * NP) return;
    int n = idx % NP, k = (idx / NP) % HH, l = idx / (NP * HH);
    int o = n >> 2, g = n & 3;
    g_wxt[idx] = (o < HH) ? A.W[g][((size_t)l * HH + o) * HH + k] : 0.f;
}
__global__ __launch_bounds__(256) void setup_bsum(XArgs A) {
    int idx = blockIdx.x * 256 + threadIdx.x;
    if (idx >= LL * NP) return;
    int n = idx % NP, l = idx / NP;
    int o = n >> 2, g = n & 3;
    g_bsum[idx] = (o < HH) ? (A.bx[g][l * HH + o] + A.bh[g][l * HH + o]) : 0.f;
}
__global__ __launch_bounds__(256) void setup_adjf(const float* __restrict__ adj) {
    int idx = blockIdx.x * 256 + threadIdx.x;
    if (idx >= 20 * 10 * 32) return;
    int lane = idx & 31, r = idx >> 5;
    int ks = r % 10, nt = r / 10;
    int gid = lane >> 2, tg = lane & 3;
    int n = nt * 8 + gid;           // output node
    int k0 = ks * 16 + 2 * tg;
    auto val = [&](int k) -> float { return (n < HH && k < HH) ? adj[n * HH + k] : 0.f; };
    uint2 b0 = split2(val(k0), val(k0 + 1));
    uint2 b1 = split2(val(k0 + 8), val(k0 + 9));
    g_adjf[idx] = make_uint4(b0.x, b1.x, b0.y, b1.y);
}
__global__ __launch_bounds__(256) void setup_wf(HArgs A) {
    int idx = blockIdx.x * 256 + threadIdx.x;
    if (idx >= LL * 80 * 10 * 32) return;
    int lane = idx & 31, r = idx >> 5;
    int ks = r % 10; r /= 10;
    int nt = r % 80;
    int l  = r / 80;
    int gid = lane >> 2, tg = lane & 3;
    int np = nt * 8 + gid;          // n' = 4*o + g
    int o = np >> 2, g = np & 3;
    int k0 = ks * 16 + 2 * tg;
    auto val = [&](int k) -> float {
        return (o < HH && k < HH) ? A.W[g][((size_t)l * HH + o) * HH + k] : 0.f;
    };
    uint2 b0 = split2(val(k0), val(k0 + 1));
    uint2 b1 = split2(val(k0 + 8), val(k0 + 9));
    g_wf[idx] = make_uint4(b0.x, b1.x, b0.y, b1.y);
}

// ---------------- kernel 1: prelude XG = x @ Wcat_x^T + (bx+bh)  (fp32, proven) ----------------
__global__ __launch_bounds__(256) void prelude2(const float* __restrict__ x) {
    const int l = blockIdx.z, nt = blockIdx.y;
    const int m0 = blockIdx.x * 64;
    const int lane = threadIdx.x & 31, wp = threadIdx.x >> 5;   // 8 warps
    const float* __restrict__ wb = g_wxt + (size_t)l * HH * NP + nt * 128 + 4 * lane;
    const float* __restrict__ xr = x + (size_t)(m0 + wp) * HH;

    float2 acc[8][2];
#pragma unroll
    for (int i = 0; i < 8; i++) { acc[i][0] = make_float2(0.f, 0.f); acc[i][1] = make_float2(0.f, 0.f); }

#pragma unroll 2
    for (int k = 0; k < HH; k++) {
        float4 b4 = *(const float4*)(wb + (size_t)k * NP);
        float2 b0 = make_float2(b4.x, b4.y), b1 = make_float2(b4.z, b4.w);
#pragma unroll
        for (int i = 0; i < 8; i++) {
            float a = __ldg(xr + i * 8 * HH + k);
            float2 a2 = make_float2(a, a);
            acc[i][0] = fma2(acc[i][0], a2, b0);
            acc[i][1] = fma2(acc[i][1], a2, b1);
        }
    }

    float* xg = (l == 0) ? g_xg0 : g_xg1;
    float4 bias = *(const float4*)(g_bsum + l * NP + nt * 128 + 4 * lane);
    if (nt < 4 || lane < 28) {
#pragma unroll
        for (int i = 0; i < 8; i++) {
            int m = m0 + wp + 8 * i;
            int b = m >> 7, t = m & 127;            // m = b*T + t
            size_t rb = ((size_t)t * BB + b) * G4 + nt * 128 + 4 * lane;
            float4 v = make_float4(acc[i][0].x + bias.x, acc[i][0].y + bias.y,
                                   acc[i][1].x + bias.z, acc[i][1].y + bias.w);
            *(float4*)(xg + rb) = v;
        }
    }
}

// ---------------- kernel 2: full recurrence via mma.sync bf16x3 ----------------
constexpr int SROWB = 336;                 // image row stride in bytes (168 bf16)
constexpr int IMG = 64 * SROWB;            // 21504 B per image
constexpr int RSMEM2 = 6 * IMG;            // 129024 B

__global__ __launch_bounds__(320, 1) void recur_mma(
        const float* __restrict__ gw1, const float* __restrict__ gw2,
        float* __restrict__ out) {
    extern __shared__ char smem[];
    const uint32_t smb = smem_u32(smem);
    const int l = blockIdx.y;
    const int r0 = blockIdx.x * 64;
    const int tid = threadIdx.x, lane = tid & 31, wid = tid >> 5;  // 10 warps
    const int gid = lane >> 2, tg = lane & 3;
    const bool evenl = ((lane & 1) == 0);
    const uint32_t loff = (uint32_t)(((lane & 7) + 8 * ((lane >> 3) & 1)) * SROWB + (lane >> 4) * 16);

    for (int i = tid; i < RSMEM2 / 4; i += 320) ((uint32_t*)smem)[i] = 0u;
    __syncthreads();

    uint32_t hH = 0, hL = IMG, cH = 2 * IMG, cL = 3 * IMG, tH = 4 * IMG, tL = 5 * IMG;

    const float c1 = gw1[l], c2 = gw2[l];
    const float* __restrict__ xg = (l == 0) ? g_xg0 : g_xg1;
    const uint4* __restrict__ wf = g_wf + (size_t)l * 80 * 10 * 32;

    // one GCN half-step: OUT[m][o] = act( w * sum_k IN[m][k] * adj[o][k] )
    auto gcn = [&](uint32_t inH, uint32_t inL, uint32_t outH, uint32_t outL, float w, bool rl) {
        float acc[2][4][4];
#pragma unroll
        for (int j = 0; j < 2; j++)
#pragma unroll
            for (int m = 0; m < 4; m++)
#pragma unroll
                for (int q = 0; q < 4; q++) acc[j][m][q] = 0.f;
#pragma unroll 1
        for (int ks = 0; ks < 10; ++ks) {
            uint32_t Ah[4][4], Al[4][4];
#pragma unroll
            for (int m = 0; m < 4; m++) {
                ldm_x4(Ah[m], smb + inH + (uint32_t)(m * 16 * SROWB + ks * 32) + loff);
                ldm_x4(Al[m], smb + inL + (uint32_t)(m * 16 * SROWB + ks * 32) + loff);
            }
#pragma unroll
            for (int j = 0; j < 2; j++) {
                uint4 B = g_adjf[((size_t)(wid + 10 * j) * 10 + ks) * 32 + lane];
#pragma unroll
                for (int m = 0; m < 4; m++) {
                    mma_bf16(acc[j][m], Ah[m], B.x, B.y);
                    mma_bf16(acc[j][m], Al[m], B.x, B.y);
                    mma_bf16(acc[j][m], Ah[m], B.z, B.w);
                }
            }
        }
#pragma unroll
        for (int j = 0; j < 2; j++) {
            int colByte = ((wid + 10 * j) * 8 + 2 * tg) * 2;
#pragma unroll
            for (int m = 0; m < 4; m++) {
                float v0 = w * acc[j][m][0], v1 = w * acc[j][m][1];
                float v2 = w * acc[j][m][2], v3 = w * acc[j][m][3];
                if (rl) {
                    v0 = fmaxf(v0, 0.f); v1 = fmaxf(v1, 0.f);
                    v2 = fmaxf(v2, 0.f); v3 = fmaxf(v3, 0.f);
                } else {
                    v0 = sigmoidf_(v0); v1 = sigmoidf_(v1);
                    v2 = sigmoidf_(v2); v3 = sigmoidf_(v3);
                }
                uint2 p01 = split2(v0, v1);
                uint2 p23 = split2(v2, v3);
                int rb0 = (m * 16 + gid) * SROWB + colByte;
                int rb1 = rb0 + 8 * SROWB;
                *(uint32_t*)(smem + outH + rb0) = p01.x;
                *(uint32_t*)(smem + outL + rb0) = p01.y;
                *(uint32_t*)(smem + outH + rb1) = p23.x;
                *(uint32_t*)(smem + outL + rb1) = p23.y;
            }
        }
    };

    // gates: preacts = h @ W^T (n' = 4o+g cols) + xg; LSTM cell update in-register
    auto gates = [&](int t) {
#pragma unroll 1
        for (int jp = 0; jp < 4; ++jp) {
            float acc[2][4][4];
#pragma unroll
            for (int j = 0; j < 2; j++)
#pragma unroll
                for (int m = 0; m < 4; m++)
#pragma unroll
                    for (int q = 0; q < 4; q++) acc[j][m][q] = 0.f;
#pragma unroll 1
            for (int ks = 0; ks < 10; ++ks) {
                uint32_t Ah[4][4], Al[4][4];
#pragma unroll
                for (int m = 0; m < 4; m++) {
                    ldm_x4(Ah[m], smb + hH + (uint32_t)(m * 16 * SROWB + ks * 32) + loff);
                    ldm_x4(Al[m], smb + hL + (uint32_t)(m * 16 * SROWB + ks * 32) + loff);
                }
#pragma unroll
                for (int j = 0; j < 2; j++) {
                    int nt = wid + 10 * j + 20 * jp;
                    uint4 B = wf[((size_t)nt * 10 + ks) * 32 + lane];
#pragma unroll
                    for (int m = 0; m < 4; m++) {
                        mma_bf16(acc[j][m], Ah[m], B.x, B.y);
                        mma_bf16(acc[j][m], Al[m], B.x, B.y);
                        mma_bf16(acc[j][m], Ah[m], B.z, B.w);
                    }
                }
            }
#pragma unroll
            for (int j = 0; j < 2; j++) {
                int nt = wid + 10 * j + 20 * jp;
                int o = 2 * nt + (tg >> 1);
#pragma unroll
                for (int m = 0; m < 4; m++) {
                    float a0 = acc[j][m][0], a1 = acc[j][m][1];
                    float a2 = acc[j][m][2], a3 = acc[j][m][3];
                    float e0 = __shfl_xor_sync(0xffffffffu, a0, 1);
                    float e1 = __shfl_xor_sync(0xffffffffu, a1, 1);
                    float e2 = __shfl_xor_sync(0xffffffffu, a2, 1);
                    float e3 = __shfl_xor_sync(0xffffffffu, a3, 1);
                    if (o < HH) {
                        int row = m * 16 + gid + (evenl ? 0 : 8);
                        float pi = evenl ? a0 : e2;
                        float pf = evenl ? a1 : e3;
                        float pc = evenl ? e0 : a2;
                        float po = evenl ? e1 : a3;
                        int grow = r0 + row;
                        const float4 xv = *(const float4*)(xg + ((size_t)t * BB + grow) * G4 + 4 * o);
                        float it = sigmoidf_(pi + xv.x);
                        float ft = sigmoidf_(pf + xv.y);
                        float cb = tanhf_fast(pc + xv.z);
                        float ot = sigmoidf_(po + xv.w);
                        int sb = row * SROWB + 2 * o;
                        float cold = __bfloat162float(*(__nv_bfloat16*)(smem + cH + sb))
                                   + __bfloat162float(*(__nv_bfloat16*)(smem + cL + sb));
                        float ct = ft * cold + it * cb;
                        float hn = ot * tanhf_fast(ct);
                        __nv_bfloat16 cth = __float2bfloat16(ct);
                        *(__nv_bfloat16*)(smem + cH + sb) = cth;
                        *(__nv_bfloat16*)(smem + cL + sb) = __float2bfloat16(ct - __bfloat162float(cth));
                        __nv_bfloat16 hnh = __float2bfloat16(hn);
                        *(__nv_bfloat16*)(smem + tH + sb) = hnh;
                        *(__nv_bfloat16*)(smem + tL + sb) = __float2bfloat16(hn - __bfloat162float(hnh));
                        if (l == 1) g_ys[((size_t)grow * TT + t) * HH + o] = hn;
                    }
                }
            }
        }
    };

    for (int t = 0; t < TT; ++t) {
        if (t > 0) {
            gcn(hH, hL, tH, tL, c1, true);  __syncthreads();
            gcn(tH, tL, hH, hL, c2, false); __syncthreads();   // H = gcn(h)
            gcn(cH, cL, tH, tL, c1, true);  __syncthreads();
            gcn(tH, tL, cH, cL, c2, false); __syncthreads();   // C = gcn(c)
        }
        gates(t);                      // reads H (A) + C (cold); writes C (ct), T (new h)
        __syncthreads();
        uint32_t s;
        s = hH; hH = tH; tH = s;
        s = hL; hL = tL; tL = s;
    }

    // final states -> h_n, c_n
    constexpr size_t OUT0 = (size_t)BB * OO * HH;
    constexpr size_t HN   = (size_t)LL * BB * HH;
    for (int i = tid; i < 64 * HH; i += 320) {
        int m = i / HH, o = i - m * HH;
        int sb = m * SROWB + 2 * o;
        float hv = __bfloat162float(*(__nv_bfloat16*)(smem + hH + sb))
                 + __bfloat162float(*(__nv_bfloat16*)(smem + hL + sb));
        float cv = __bfloat162float(*(__nv_bfloat16*)(smem + cH + sb))
                 + __bfloat162float(*(__nv_bfloat16*)(smem + cL + sb));
        size_t off = ((size_t)l * BB + (r0 + m)) * HH + o;
        out[OUT0 + off]      = hv;
        out[OUT0 + HN + off] = cv;
    }
}

// ---------------- kernel 3: output projection ----------------
constexpr int YROW = TT * HH;  // 19968
constexpr int OSMEM = (YROW + OO * TT + OO) * 4;

__global__ __launch_bounds__(256) void out_kernel(const float* __restrict__ Wout,
                                                  const float* __restrict__ bout,
                                                  float* __restrict__ out) {
    extern __shared__ float sm[];
    float* sy = sm;
    float* sw = sm + YROW;
    float* sb = sw + OO * TT;
    const int b = blockIdx.x;
    const int tid = threadIdx.x;
    const float* yb = g_ys + (size_t)b * YROW;
    for (int i = tid; i < YROW / 4; i += 256) ((float4*)sy)[i] = ((const float4*)yb)[i];
    for (int i = tid; i < OO * TT; i += 256) sw[i] = Wout[i];
    if (tid < OO) sb[tid] = bout[tid];
    __syncthreads();
    for (int idx = tid; idx < HH * OO; idx += 256) {
        int f = idx / OO, jj = idx - f * OO;
        const float* yr = sy + f * TT;
        const float* wr = sw + jj * TT;
        float2 a = make_float2(0.f, 0.f);
#pragma unroll 4
        for (int p = 0; p < TT / 2; ++p)
            a = fma2(a, *(const float2*)(yr + 2 * p), *(const float2*)(wr + 2 * p));
        out[(size_t)b * (HH * OO) + idx] = a.x + a.y + sb[jj];
    }
}

// ---------------- launcher ----------------
extern "C" void kernel_launch(void* const* d_in, const int* in_sizes, int n_in,
                              void* d_out, int out_size) {
    const float* x   = (const float*)d_in[0];
    const float* adj = (const float*)d_in[1];

    XArgs xa;
    xa.W[0] = (const float*)d_in[2];  xa.bx[0] = (const float*)d_in[3];
    xa.W[1] = (const float*)d_in[6];  xa.bx[1] = (const float*)d_in[7];
    xa.W[2] = (const float*)d_in[10]; xa.bx[2] = (const float*)d_in[11];
    xa.W[3] = (const float*)d_in[14]; xa.bx[3] = (const float*)d_in[15];
    xa.bh[0] = (const float*)d_in[5];
    xa.bh[1] = (const float*)d_in[9];
    xa.bh[2] = (const float*)d_in[13];
    xa.bh[3] = (const float*)d_in[17];

    HArgs ha;
    ha.W[0] = (const float*)d_in[4];
    ha.W[1] = (const float*)d_in[8];
    ha.W[2] = (const float*)d_in[12];
    ha.W[3] = (const float*)d_in[16];

    const float* gw1  = (const float*)d_in[18];
    const float* gw2  = (const float*)d_in[19];
    const float* Wout = (const float*)d_in[20];
    const float* bout = (const float*)d_in[21];
    float* out = (float*)d_out;

    cudaFuncSetAttribute(recur_mma,  cudaFuncAttributeMaxDynamicSharedMemorySize, RSMEM2);
    cudaFuncSetAttribute(out_kernel, cudaFuncAttributeMaxDynamicSharedMemorySize, OSMEM);

    setup_wxt <<<(LL * HH * NP + 255) / 256, 256>>>(xa);
    setup_bsum<<<(LL * NP + 255) / 256, 256>>>(xa);
    setup_adjf<<<(20 * 10 * 32 + 255) / 256, 256>>>(adj);
    setup_wf  <<<(LL * 80 * 10 * 32 + 255) / 256, 256>>>(ha);

    dim3 pg(BB * TT / 64, 5, LL);            // 8192 x 5 x 2
    prelude2<<<pg, 256>>>(x);

    dim3 rg(BB / 64, LL);                    // 64 x 2 = 128 blocks
    recur_mma<<<rg, 320, RSMEM2>>>(gw1, gw2, out);

    out_kernel<<<BB, 256, OSMEM>>>(Wout, bout, out);
}

// round 10
// speedup vs baseline: 5.3753x; 1.3825x over previous
#include <cuda_runtime.h>
#include <cuda_bf16.h>
#include <cuda_fp16.h>
#include <cstddef>
#include <cstdint>

// Problem dims
constexpr int BB = 4096;   // batch
constexpr int TT = 128;    // time
constexpr int HH = 156;    // hidden/nodes
constexpr int LL = 2;      // layers
constexpr int OO = 12;     // output len
constexpr int G4 = 4 * HH; // 624  (gate cols, ordered n' = 4*o + g; g: 0=i,1=f,2=c,3=o)
constexpr int NP = 640;    // padded gate width

// Scratch (device globals)
constexpr size_t XG_ELEMS = (size_t)TT * BB * G4;      // ~1.22 GiB each
__device__ float g_xg0[XG_ELEMS];
__device__ float g_xg1[XG_ELEMS];
__device__ float g_ys[(size_t)BB * TT * HH];           // ~312 MiB

// Preprocessed data
__device__ float g_bsum[LL * NP];             // bx+bh in n' order
// fragment packs (fp16). adj/h-weights: hi only (uint2). x-weights: hi+lo (uint4).
__device__ uint2 g_adjf2[20 * 10 * 32];       // adj^T fragments
__device__ uint2 g_wf2[LL * 80 * 10 * 32];    // h-weight fragments
__device__ uint4 g_wxf[LL * 80 * 10 * 32];    // x-weight fragments {b0h,b1h,b0l,b1l}

// ---------------- generic helpers ----------------
__device__ __forceinline__ float2 fma2(float2 d, float2 a, float2 b) {
    unsigned long long dd = *reinterpret_cast<unsigned long long*>(&d);
    unsigned long long aa = *reinterpret_cast<unsigned long long*>(&a);
    unsigned long long bb = *reinterpret_cast<unsigned long long*>(&b);
    asm("fma.rn.f32x2 %0, %1, %2, %0;" : "+l"(dd) : "l"(aa), "l"(bb));
    return *reinterpret_cast<float2*>(&dd);
}
__device__ __forceinline__ float sigmoidf_(float x) {
    return __fdividef(1.0f, 1.0f + __expf(-x));
}
__device__ __forceinline__ float tanhf_fast(float x) {
    float ax = fabsf(x);
    float e = __expf(-2.0f * ax);
    float t = __fdividef(1.0f - e, 1.0f + e);
    return copysignf(t, x);
}
__device__ __forceinline__ uint32_t smem_u32(const void* p) {
    uint32_t a;
    asm("{ .reg .u64 t; cvta.to.shared.u64 t, %1; cvt.u32.u64 %0, t; }" : "=r"(a) : "l"(p));
    return a;
}
__device__ __forceinline__ uint32_t packh(float a, float b) {
    __half ha = __float2half_rn(a), hb = __float2half_rn(b);
    return (uint32_t)__half_as_ushort(ha) | ((uint32_t)__half_as_ushort(hb) << 16);
}
// split (x,y) into packed fp16 hi / fp16 lo residual pairs
__device__ __forceinline__ uint2 split2h(float x, float y) {
    __half hx = __float2half_rn(x), hy = __float2half_rn(y);
    float rx = x - __half2float(hx), ry = y - __half2float(hy);
    uint2 r;
    r.x = (uint32_t)__half_as_ushort(hx) | ((uint32_t)__half_as_ushort(hy) << 16);
    r.y = (uint32_t)__half_as_ushort(__float2half_rn(rx)) |
          ((uint32_t)__half_as_ushort(__float2half_rn(ry)) << 16);
    return r;
}
__device__ __forceinline__ void ldm_x4(uint32_t* r, uint32_t addr) {
    asm volatile("ldmatrix.sync.aligned.m8n8.x4.shared.b16 {%0,%1,%2,%3}, [%4];"
                 : "=r"(r[0]), "=r"(r[1]), "=r"(r[2]), "=r"(r[3]) : "r"(addr));
}
__device__ __forceinline__ void mma_f16(float* c, const uint32_t* a, uint32_t b0, uint32_t b1) {
    asm volatile(
        "mma.sync.aligned.m16n8k16.row.col.f32.f16.f16.f32 "
        "{%0,%1,%2,%3}, {%4,%5,%6,%7}, {%8,%9}, {%0,%1,%2,%3};"
        : "+f"(c[0]), "+f"(c[1]), "+f"(c[2]), "+f"(c[3])
        : "r"(a[0]), "r"(a[1]), "r"(a[2]), "r"(a[3]), "r"(b0), "r"(b1));
}

struct XArgs {
    const float* W[4];   // Wix, Wfx, Wcx, Wox   each [L,H,H]
    const float* bx[4];
    const float* bh[4];
};
struct HArgs {
    const float* W[4];   // Wih, Wfh, Wch, Woh  each [L,H,H]
};

// ---------------- setup kernels ----------------
__global__ __launch_bounds__(256) void setup_bsum(XArgs A) {
    int idx = blockIdx.x * 256 + threadIdx.x;
    if (idx >= LL * NP) return;
    int n = idx % NP, l = idx / NP;
    int o = n >> 2, g = n & 3;
    g_bsum[idx] = (o < HH) ? (A.bx[g][l * HH + o] + A.bh[g][l * HH + o]) : 0.f;
}
__global__ __launch_bounds__(256) void setup_adjf2(const float* __restrict__ adj) {
    int idx = blockIdx.x * 256 + threadIdx.x;
    if (idx >= 20 * 10 * 32) return;
    int lane = idx & 31, r = idx >> 5;
    int ks = r % 10, nt = r / 10;
    int gid = lane >> 2, tg = lane & 3;
    int n = nt * 8 + gid;           // output node
    int k0 = ks * 16 + 2 * tg;
    auto val = [&](int k) -> float { return (n < HH && k < HH) ? adj[n * HH + k] : 0.f; };
    g_adjf2[idx] = make_uint2(packh(val(k0), val(k0 + 1)), packh(val(k0 + 8), val(k0 + 9)));
}
__global__ __launch_bounds__(256) void setup_wf2(HArgs A) {
    int idx = blockIdx.x * 256 + threadIdx.x;
    if (idx >= LL * 80 * 10 * 32) return;
    int lane = idx & 31, r = idx >> 5;
    int ks = r % 10; r /= 10;
    int nt = r % 80;
    int l  = r / 80;
    int gid = lane >> 2, tg = lane & 3;
    int np = nt * 8 + gid;          // n' = 4*o + g
    int o = np >> 2, g = np & 3;
    int k0 = ks * 16 + 2 * tg;
    auto val = [&](int k) -> float {
        return (o < HH && k < HH) ? A.W[g][((size_t)l * HH + o) * HH + k] : 0.f;
    };
    g_wf2[idx] = make_uint2(packh(val(k0), val(k0 + 1)), packh(val(k0 + 8), val(k0 + 9)));
}
__global__ __launch_bounds__(256) void setup_wxf(XArgs A) {
    int idx = blockIdx.x * 256 + threadIdx.x;
    if (idx >= LL * 80 * 10 * 32) return;
    int lane = idx & 31, r = idx >> 5;
    int ks = r % 10; r /= 10;
    int nt = r % 80;
    int l  = r / 80;
    int gid = lane >> 2, tg = lane & 3;
    int np = nt * 8 + gid;          // n' = 4*o + g
    int o = np >> 2, g = np & 3;
    int k0 = ks * 16 + 2 * tg;
    auto val = [&](int k) -> float {
        return (o < HH && k < HH) ? A.W[g][((size_t)l * HH + o) * HH + k] : 0.f;
    };
    float v0 = val(k0), v1 = val(k0 + 1), v2 = val(k0 + 8), v3 = val(k0 + 9);
    uint2 p0 = split2h(v0, v1);
    uint2 p1 = split2h(v2, v3);
    g_wxf[idx] = make_uint4(p0.x, p1.x, p0.y, p1.y);
}

// ---------------- shared layout constants ----------------
constexpr int SROWB = 336;                 // image row stride in bytes (168 fp16)
constexpr int IMG = 64 * SROWB;            // 21504 B per image

// ---------------- kernel 1: prelude XG = x @ Wcat_x^T + bias  (fp16x3 HMMA) ----------------
__global__ __launch_bounds__(320, 1) void prelude_hmma(const float* __restrict__ x) {
    __shared__ char psm[2 * IMG];          // x images hi/lo (43008 B)
    const uint32_t smb = smem_u32(psm);
    const int l = blockIdx.y;
    const int m0 = blockIdx.x * 64;
    const int tid = threadIdx.x, lane = tid & 31, wid = tid >> 5;  // 10 warps
    const int gid = lane >> 2, tg = lane & 3;
    const uint32_t loff = (uint32_t)(((lane & 7) + 8 * ((lane >> 3) & 1)) * SROWB + (lane >> 4) * 16);

    // stage x rows -> hi/lo fp16 images (pad k 156..159 with zeros)
    for (int idx = tid; idx < 64 * 80; idx += 320) {
        int r = idx / 80, c2 = idx % 80;
        uint2 p = make_uint2(0u, 0u);
        if (c2 < 78) {
            float2 v = *(const float2*)(x + (size_t)(m0 + r) * HH + 2 * c2);
            p = split2h(v.x, v.y);
        }
        *(uint32_t*)(psm + r * SROWB + 4 * c2) = p.x;
        *(uint32_t*)(psm + IMG + r * SROWB + 4 * c2) = p.y;
    }
    __syncthreads();

    float* __restrict__ xg = (l == 0) ? g_xg0 : g_xg1;
    const uint4* __restrict__ wf = g_wxf + (size_t)l * 80 * 10 * 32;

#pragma unroll 1
    for (int hf = 0; hf < 2; ++hf) {
        float acc[4][4][4];
#pragma unroll
        for (int u = 0; u < 4; u++)
#pragma unroll
            for (int m = 0; m < 4; m++)
#pragma unroll
                for (int q = 0; q < 4; q++) acc[u][m][q] = 0.f;

#pragma unroll 1
        for (int ks = 0; ks < 10; ++ks) {
            uint32_t Ah[4][4], Al[4][4];
#pragma unroll
            for (int m = 0; m < 4; m++) {
                ldm_x4(Ah[m], smb + (uint32_t)(m * 16 * SROWB + ks * 32) + loff);
                ldm_x4(Al[m], smb + (uint32_t)(IMG + m * 16 * SROWB + ks * 32) + loff);
            }
#pragma unroll
            for (int u = 0; u < 4; ++u) {
                int nt = wid + 10 * (4 * hf + u);
                uint4 B = wf[((size_t)nt * 10 + ks) * 32 + lane];
#pragma unroll
                for (int m = 0; m < 4; m++) {
                    mma_f16(acc[u][m], Ah[m], B.x, B.y);   // Ah*Bh
                    mma_f16(acc[u][m], Al[m], B.x, B.y);   // Al*Bh
                    mma_f16(acc[u][m], Ah[m], B.z, B.w);   // Ah*Bl
                }
            }
        }
        // epilogue: add bias, store fp32 to xg
#pragma unroll
        for (int u = 0; u < 4; ++u) {
            int nt = wid + 10 * (4 * hf + u);
            int n0 = 8 * nt + 2 * tg;
            if (n0 < G4) {
                float2 bias = *(const float2*)(g_bsum + l * NP + n0);
#pragma unroll
                for (int m = 0; m < 4; m++) {
                    int mr0 = m0 + m * 16 + gid;
                    int b0i = mr0 >> 7, t0i = mr0 & 127;
                    float2 v0 = make_float2(acc[u][m][0] + bias.x, acc[u][m][1] + bias.y);
                    *(float2*)(xg + ((size_t)t0i * BB + b0i) * G4 + n0) = v0;
                    int mr1 = mr0 + 8;
                    int b1i = mr1 >> 7, t1i = mr1 & 127;
                    float2 v1 = make_float2(acc[u][m][2] + bias.x, acc[u][m][3] + bias.y);
                    *(float2*)(xg + ((size_t)t1i * BB + b1i) * G4 + n0) = v1;
                }
            }
        }
    }
}

// ---------------- kernel 2: full recurrence via mma.sync fp16x2 ----------------
constexpr int RSMEM2 = 6 * IMG;            // 129024 B

__global__ __launch_bounds__(320, 1) void recur_mma(
        const float* __restrict__ gw1, const float* __restrict__ gw2,
        float* __restrict__ out) {
    extern __shared__ char smem[];
    const uint32_t smb = smem_u32(smem);
    const int l = blockIdx.y;
    const int r0 = blockIdx.x * 64;
    const int tid = threadIdx.x, lane = tid & 31, wid = tid >> 5;  // 10 warps
    const int gid = lane >> 2, tg = lane & 3;
    const bool evenl = ((lane & 1) == 0);
    const uint32_t loff = (uint32_t)(((lane & 7) + 8 * ((lane >> 3) & 1)) * SROWB + (lane >> 4) * 16);

    for (int i = tid; i < RSMEM2 / 4; i += 320) ((uint32_t*)smem)[i] = 0u;
    __syncthreads();

    uint32_t hH = 0, hL = IMG, cH = 2 * IMG, cL = 3 * IMG, tH = 4 * IMG, tL = 5 * IMG;

    const float c1 = gw1[l], c2 = gw2[l];
    const float* __restrict__ xg = (l == 0) ? g_xg0 : g_xg1;
    const uint2* __restrict__ wf = g_wf2 + (size_t)l * 80 * 10 * 32;

    // one GCN half-step: OUT[m][o] = act( w * sum_k IN[m][k] * adj[o][k] )
    auto gcn = [&](uint32_t inH, uint32_t inL, uint32_t outH, uint32_t outL, float w, bool rl) {
        float acc[2][4][4];
#pragma unroll
        for (int j = 0; j < 2; j++)
#pragma unroll
            for (int m = 0; m < 4; m++)
#pragma unroll
                for (int q = 0; q < 4; q++) acc[j][m][q] = 0.f;
#pragma unroll 1
        for (int ks = 0; ks < 10; ++ks) {
            uint32_t Ah[4][4], Al[4][4];
#pragma unroll
            for (int m = 0; m < 4; m++) {
                ldm_x4(Ah[m], smb + inH + (uint32_t)(m * 16 * SROWB + ks * 32) + loff);
                ldm_x4(Al[m], smb + inL + (uint32_t)(m * 16 * SROWB + ks * 32) + loff);
            }
#pragma unroll
            for (int j = 0; j < 2; j++) {
                uint2 B = g_adjf2[((size_t)(wid + 10 * j) * 10 + ks) * 32 + lane];
#pragma unroll
                for (int m = 0; m < 4; m++) {
                    mma_f16(acc[j][m], Ah[m], B.x, B.y);
                    mma_f16(acc[j][m], Al[m], B.x, B.y);
                }
            }
        }
#pragma unroll
        for (int j = 0; j < 2; j++) {
            int colByte = ((wid + 10 * j) * 8 + 2 * tg) * 2;
#pragma unroll
            for (int m = 0; m < 4; m++) {
                float v0 = w * acc[j][m][0], v1 = w * acc[j][m][1];
                float v2 = w * acc[j][m][2], v3 = w * acc[j][m][3];
                if (rl) {
                    v0 = fmaxf(v0, 0.f); v1 = fmaxf(v1, 0.f);
                    v2 = fmaxf(v2, 0.f); v3 = fmaxf(v3, 0.f);
                } else {
                    v0 = sigmoidf_(v0); v1 = sigmoidf_(v1);
                    v2 = sigmoidf_(v2); v3 = sigmoidf_(v3);
                }
                uint2 p01 = split2h(v0, v1);
                uint2 p23 = split2h(v2, v3);
                int rb0 = (m * 16 + gid) * SROWB + colByte;
                int rb1 = rb0 + 8 * SROWB;
                *(uint32_t*)(smem + outH + rb0) = p01.x;
                *(uint32_t*)(smem + outL + rb0) = p01.y;
                *(uint32_t*)(smem + outH + rb1) = p23.x;
                *(uint32_t*)(smem + outL + rb1) = p23.y;
            }
        }
    };

    // gates: preacts = h @ W^T (n' = 4o+g cols) + xg; LSTM cell update in-register
    auto gates = [&](int t) {
#pragma unroll 1
        for (int hf = 0; hf < 2; ++hf) {
            float acc[4][4][4];
#pragma unroll
            for (int u = 0; u < 4; u++)
#pragma unroll
                for (int m = 0; m < 4; m++)
#pragma unroll
                    for (int q = 0; q < 4; q++) acc[u][m][q] = 0.f;
#pragma unroll 1
            for (int ks = 0; ks < 10; ++ks) {
                uint32_t Ah[4][4], Al[4][4];
#pragma unroll
                for (int m = 0; m < 4; m++) {
                    ldm_x4(Ah[m], smb + hH + (uint32_t)(m * 16 * SROWB + ks * 32) + loff);
                    ldm_x4(Al[m], smb + hL + (uint32_t)(m * 16 * SROWB + ks * 32) + loff);
                }
#pragma unroll
                for (int u = 0; u < 4; ++u) {
                    int nt = wid + 10 * (4 * hf + u);
                    uint2 B = wf[((size_t)nt * 10 + ks) * 32 + lane];
#pragma unroll
                    for (int m = 0; m < 4; m++) {
                        mma_f16(acc[u][m], Ah[m], B.x, B.y);
                        mma_f16(acc[u][m], Al[m], B.x, B.y);
                    }
                }
            }
#pragma unroll
            for (int u = 0; u < 4; ++u) {
                int nt = wid + 10 * (4 * hf + u);
                int o = 2 * nt + (tg >> 1);
#pragma unroll
                for (int m = 0; m < 4; m++) {
                    float a0 = acc[u][m][0], a1 = acc[u][m][1];
                    float a2 = acc[u][m][2], a3 = acc[u][m][3];
                    float e0 = __shfl_xor_sync(0xffffffffu, a0, 1);
                    float e1 = __shfl_xor_sync(0xffffffffu, a1, 1);
                    float e2 = __shfl_xor_sync(0xffffffffu, a2, 1);
                    float e3 = __shfl_xor_sync(0xffffffffu, a3, 1);
                    if (o < HH) {
                        int row = m * 16 + gid + (evenl ? 0 : 8);
                        float pi = evenl ? a0 : e2;
                        float pf = evenl ? a1 : e3;
                        float pc = evenl ? e0 : a2;
                        float po = evenl ? e1 : a3;
                        int grow = r0 + row;
                        const float4 xv = *(const float4*)(xg + ((size_t)t * BB + grow) * G4 + 4 * o);
                        float it = sigmoidf_(pi + xv.x);
                        float ft = sigmoidf_(pf + xv.y);
                        float cb = tanhf_fast(pc + xv.z);
                        float ot = sigmoidf_(po + xv.w);
                        int sb = row * SROWB + 2 * o;
                        float cold = __half2float(*(__half*)(smem + cH + sb))
                                   + __half2float(*(__half*)(smem + cL + sb));
                        float ct = ft * cold + it * cb;
                        float hn = ot * tanhf_fast(ct);
                        __half cth = __float2half_rn(ct);
                        *(__half*)(smem + cH + sb) = cth;
                        *(__half*)(smem + cL + sb) = __float2half_rn(ct - __half2float(cth));
                        __half hnh = __float2half_rn(hn);
                        *(__half*)(smem + tH + sb) = hnh;
                        *(__half*)(smem + tL + sb) = __float2half_rn(hn - __half2float(hnh));
                        if (l == 1) g_ys[((size_t)grow * TT + t) * HH + o] = hn;
                    }
                }
            }
        }
    };

    for (int t = 0; t < TT; ++t) {
        if (t > 0) {
            gcn(hH, hL, tH, tL, c1, true);  __syncthreads();
            gcn(tH, tL, hH, hL, c2, false); __syncthreads();   // H = gcn(h)
            gcn(cH, cL, tH, tL, c1, true);  __syncthreads();
            gcn(tH, tL, cH, cL, c2, false); __syncthreads();   // C = gcn(c)
        }
        gates(t);                      // reads H (A) + C (cold); writes C (ct), T (new h)
        __syncthreads();
        uint32_t s;
        s = hH; hH = tH; tH = s;
        s = hL; hL = tL; tL = s;
    }

    // final states -> h_n, c_n
    constexpr size_t OUT0 = (size_t)BB * OO * HH;
    constexpr size_t HN   = (size_t)LL * BB * HH;
    for (int i = tid; i < 64 * HH; i += 320) {
        int m = i / HH, o = i - m * HH;
        int sb = m * SROWB + 2 * o;
        float hv = __half2float(*(__half*)(smem + hH + sb))
                 + __half2float(*(__half*)(smem + hL + sb));
        float cv = __half2float(*(__half*)(smem + cH + sb))
                 + __half2float(*(__half*)(smem + cL + sb));
        size_t off = ((size_t)l * BB + (r0 + m)) * HH + o;
        out[OUT0 + off]      = hv;
        out[OUT0 + HN + off] = cv;
    }
}

// ---------------- kernel 3: output projection ----------------
constexpr int YROW = TT * HH;  // 19968
constexpr int OSMEM = (YROW + OO * TT + OO) * 4;

__global__ __launch_bounds__(256) void out_kernel(const float* __restrict__ Wout,
                                                  const float* __restrict__ bout,
                                                  float* __restrict__ out) {
    extern __shared__ float sm[];
    float* sy = sm;
    float* sw = sm + YROW;
    float* sb = sw + OO * TT;
    const int b = blockIdx.x;
    const int tid = threadIdx.x;
    const float* yb = g_ys + (size_t)b * YROW;
    for (int i = tid; i < YROW / 4; i += 256) ((float4*)sy)[i] = ((const float4*)yb)[i];
    for (int i = tid; i < OO * TT; i += 256) sw[i] = Wout[i];
    if (tid < OO) sb[tid] = bout[tid];
    __syncthreads();
    for (int idx = tid; idx < HH * OO; idx += 256) {
        int f = idx / OO, jj = idx - f * OO;
        const float* yr = sy + f * TT;
        const float* wr = sw + jj * TT;
        float2 a = make_float2(0.f, 0.f);
#pragma unroll 4
        for (int p = 0; p < TT / 2; ++p)
            a = fma2(a, *(const float2*)(yr + 2 * p), *(const float2*)(wr + 2 * p));
        out[(size_t)b * (HH * OO) + idx] = a.x + a.y + sb[jj];
    }
}

// ---------------- launcher ----------------
extern "C" void kernel_launch(void* const* d_in, const int* in_sizes, int n_in,
                              void* d_out, int out_size) {
    const float* x   = (const float*)d_in[0];
    const float* adj = (const float*)d_in[1];

    XArgs xa;
    xa.W[0] = (const float*)d_in[2];  xa.bx[0] = (const float*)d_in[3];
    xa.W[1] = (const float*)d_in[6];  xa.bx[1] = (const float*)d_in[7];
    xa.W[2] = (const float*)d_in[10]; xa.bx[2] = (const float*)d_in[11];
    xa.W[3] = (const float*)d_in[14]; xa.bx[3] = (const float*)d_in[15];
    xa.bh[0] = (const float*)d_in[5];
    xa.bh[1] = (const float*)d_in[9];
    xa.bh[2] = (const float*)d_in[13];
    xa.bh[3] = (const float*)d_in[17];

    HArgs ha;
    ha.W[0] = (const float*)d_in[4];
    ha.W[1] = (const float*)d_in[8];
    ha.W[2] = (const float*)d_in[12];
    ha.W[3] = (const float*)d_in[16];

    const float* gw1  = (const float*)d_in[18];
    const float* gw2  = (const float*)d_in[19];
    const float* Wout = (const float*)d_in[20];
    const float* bout = (const float*)d_in[21];
    float* out = (float*)d_out;

    cudaFuncSetAttribute(recur_mma,  cudaFuncAttributeMaxDynamicSharedMemorySize, RSMEM2);
    cudaFuncSetAttribute(out_kernel, cudaFuncAttributeMaxDynamicSharedMemorySize, OSMEM);

    setup_bsum <<<(LL * NP + 255) / 256, 256>>>(xa);
    setup_adjf2<<<(20 * 10 * 32 + 255) / 256, 256>>>(adj);
    setup_wf2  <<<(LL * 80 * 10 * 32 + 255) / 256, 256>>>(ha);
    setup_wxf  <<<(LL * 80 * 10 * 32 + 255) / 256, 256>>>(xa);

    dim3 pg(BB * TT / 64, LL);               // 8192 x 2 CTAs
    prelude_hmma<<<pg, 320>>>(x);

    dim3 rg(BB / 64, LL);                    // 64 x 2 = 128 blocks
    recur_mma<<<rg, 320, RSMEM2>>>(gw1, gw2, out);

    out_kernel<<<BB, 256, OSMEM>>>(Wout, bout, out);
}

// round 14
// speedup vs baseline: 6.9630x; 1.2954x over previous
#include <cuda_runtime.h>
#include <cuda_bf16.h>
#include <cuda_fp16.h>
#include <cstddef>
#include <cstdint>

// Problem dims
constexpr int BB = 4096;   // batch
constexpr int TT = 128;    // time
constexpr int HH = 156;    // hidden/nodes
constexpr int LL = 2;      // layers
constexpr int OO = 12;     // output len
constexpr int G4 = 4 * HH; // 624  (gate cols, ordered n' = 4*o + g; g: 0=i,1=f,2=c,3=o)
constexpr int NP = 640;    // padded gate width

// Scratch (device globals)
constexpr size_t XG_ELEMS = (size_t)TT * BB * G4;      // ~1.22 GiB each
__device__ float g_xg0[XG_ELEMS];
__device__ float g_xg1[XG_ELEMS];
__device__ float g_ys[(size_t)BB * TT * HH];           // ~312 MiB

// Preprocessed data
__device__ float g_bsum[LL * NP];             // bx+bh in n' order
// fragment packs (fp16). adj/h-weights: hi only (uint2). x-weights: hi+lo (uint4).
__device__ uint2 g_adjf2[20 * 10 * 32];       // adj^T fragments
__device__ uint2 g_wf2[LL * 80 * 10 * 32];    // h-weight fragments
__device__ uint4 g_wxf[LL * 80 * 10 * 32];    // x-weight fragments {b0h,b1h,b0l,b1l}

// ---------------- generic helpers ----------------
__device__ __forceinline__ float2 fma2(float2 d, float2 a, float2 b) {
    unsigned long long dd = *reinterpret_cast<unsigned long long*>(&d);
    unsigned long long aa = *reinterpret_cast<unsigned long long*>(&a);
    unsigned long long bb = *reinterpret_cast<unsigned long long*>(&b);
    asm("fma.rn.f32x2 %0, %1, %2, %0;" : "+l"(dd) : "l"(aa), "l"(bb));
    return *reinterpret_cast<float2*>(&dd);
}
__device__ __forceinline__ float sigmoidf_(float x) {
    return __fdividef(1.0f, 1.0f + __expf(-x));
}
__device__ __forceinline__ float tanhf_fast(float x) {
    float ax = fabsf(x);
    float e = __expf(-2.0f * ax);
    float t = __fdividef(1.0f - e, 1.0f + e);
    return copysignf(t, x);
}
__device__ __forceinline__ uint32_t smem_u32(const void* p) {
    uint32_t a;
    asm("{ .reg .u64 t; cvta.to.shared.u64 t, %1; cvt.u32.u64 %0, t; }" : "=r"(a) : "l"(p));
    return a;
}
__device__ __forceinline__ uint32_t packh(float a, float b) {
    __half ha = __float2half_rn(a), hb = __float2half_rn(b);
    return (uint32_t)__half_as_ushort(ha) | ((uint32_t)__half_as_ushort(hb) << 16);
}
// split (x,y) into packed fp16 hi / fp16 lo residual pairs
__device__ __forceinline__ uint2 split2h(float x, float y) {
    __half hx = __float2half_rn(x), hy = __float2half_rn(y);
    float rx = x - __half2float(hx), ry = y - __half2float(hy);
    uint2 r;
    r.x = (uint32_t)__half_as_ushort(hx) | ((uint32_t)__half_as_ushort(hy) << 16);
    r.y = (uint32_t)__half_as_ushort(__float2half_rn(rx)) |
          ((uint32_t)__half_as_ushort(__float2half_rn(ry)) << 16);
    return r;
}
__device__ __forceinline__ void ldm_x4(uint32_t* r, uint32_t addr) {
    asm volatile("ldmatrix.sync.aligned.m8n8.x4.shared.b16 {%0,%1,%2,%3}, [%4];"
                 : "=r"(r[0]), "=r"(r[1]), "=r"(r[2]), "=r"(r[3]) : "r"(addr));
}
__device__ __forceinline__ void mma_f16(float* c, const uint32_t* a, uint32_t b0, uint32_t b1) {
    asm volatile(
        "mma.sync.aligned.m16n8k16.row.col.f32.f16.f16.f32 "
        "{%0,%1,%2,%3}, {%4,%5,%6,%7}, {%8,%9}, {%0,%1,%2,%3};"
        : "+f"(c[0]), "+f"(c[1]), "+f"(c[2]), "+f"(c[3])
        : "r"(a[0]), "r"(a[1]), "r"(a[2]), "r"(a[3]), "r"(b0), "r"(b1));
}

struct XArgs {
    const float* W[4];   // Wix, Wfx, Wcx, Wox   each [L,H,H]
    const float* bx[4];
    const float* bh[4];
};
struct HArgs {
    const float* W[4];   // Wih, Wfh, Wch, Woh  each [L,H,H]
};

// ---------------- setup kernels ----------------
__global__ __launch_bounds__(256) void setup_bsum(XArgs A) {
    int idx = blockIdx.x * 256 + threadIdx.x;
    if (idx >= LL * NP) return;
    int n = idx % NP, l = idx / NP;
    int o = n >> 2, g = n & 3;
    g_bsum[idx] = (o < HH) ? (A.bx[g][l * HH + o] + A.bh[g][l * HH + o]) : 0.f;
}
__global__ __launch_bounds__(256) void setup_adjf2(const float* __restrict__ adj) {
    int idx = blockIdx.x * 256 + threadIdx.x;
    if (idx >= 20 * 10 * 32) return;
    int lane = idx & 31, r = idx >> 5;
    int ks = r % 10, nt = r / 10;
    int gid = lane >> 2, tg = lane & 3;
    int n = nt * 8 + gid;           // output node
    int k0 = ks * 16 + 2 * tg;
    auto val = [&](int k) -> float { return (n < HH && k < HH) ? adj[n * HH + k] : 0.f; };
    g_adjf2[idx] = make_uint2(packh(val(k0), val(k0 + 1)), packh(val(k0 + 8), val(k0 + 9)));
}
__global__ __launch_bounds__(256) void setup_wf2(HArgs A) {
    int idx = blockIdx.x * 256 + threadIdx.x;
    if (idx >= LL * 80 * 10 * 32) return;
    int lane = idx & 31, r = idx >> 5;
    int ks = r % 10; r /= 10;
    int nt = r % 80;
    int l  = r / 80;
    int gid = lane >> 2, tg = lane & 3;
    int np = nt * 8 + gid;          // n' = 4*o + g
    int o = np >> 2, g = np & 3;
    int k0 = ks * 16 + 2 * tg;
    auto val = [&](int k) -> float {
        return (o < HH && k < HH) ? A.W[g][((size_t)l * HH + o) * HH + k] : 0.f;
    };
    g_wf2[idx] = make_uint2(packh(val(k0), val(k0 + 1)), packh(val(k0 + 8), val(k0 + 9)));
}
__global__ __launch_bounds__(256) void setup_wxf(XArgs A) {
    int idx = blockIdx.x * 256 + threadIdx.x;
    if (idx >= LL * 80 * 10 * 32) return;
    int lane = idx & 31, r = idx >> 5;
    int ks = r % 10; r /= 10;
    int nt = r % 80;
    int l  = r / 80;
    int gid = lane >> 2, tg = lane & 3;
    int np = nt * 8 + gid;          // n' = 4*o + g
    int o = np >> 2, g = np & 3;
    int k0 = ks * 16 + 2 * tg;
    auto val = [&](int k) -> float {
        return (o < HH && k < HH) ? A.W[g][((size_t)l * HH + o) * HH + k] : 0.f;
    };
    float v0 = val(k0), v1 = val(k0 + 1), v2 = val(k0 + 8), v3 = val(k0 + 9);
    uint2 p0 = split2h(v0, v1);
    uint2 p1 = split2h(v2, v3);
    g_wxf[idx] = make_uint4(p0.x, p1.x, p0.y, p1.y);
}

// ---------------- shared layout constants ----------------
constexpr int SROWB = 336;                 // image row stride in bytes (168 fp16)
constexpr int IMG = 64 * SROWB;            // prelude image (64 rows)
constexpr int IMGR = 32 * SROWB;           // recurrence image (32 rows) = 10752 B
constexpr int RSMEM2 = 8 * IMGR;           // 86016 B

// ---------------- kernel 1: prelude XG = x @ Wcat_x^T + bias  (fp16x3 HMMA) ----------------
__global__ __launch_bounds__(320, 1) void prelude_hmma(const float* __restrict__ x) {
    __shared__ char psm[2 * IMG];          // x images hi/lo (43008 B)
    const uint32_t smb = smem_u32(psm);
    const int l = blockIdx.y;
    const int m0 = blockIdx.x * 64;
    const int tid = threadIdx.x, lane = tid & 31, wid = tid >> 5;  // 10 warps
    const int gid = lane >> 2, tg = lane & 3;
    const uint32_t loff = (uint32_t)(((lane & 7) + 8 * ((lane >> 3) & 1)) * SROWB + (lane >> 4) * 16);

    // stage x rows -> hi/lo fp16 images (pad k 156..159 with zeros)
    for (int idx = tid; idx < 64 * 80; idx += 320) {
        int r = idx / 80, c2 = idx % 80;
        uint2 p = make_uint2(0u, 0u);
        if (c2 < 78) {
            float2 v = *(const float2*)(x + (size_t)(m0 + r) * HH + 2 * c2);
            p = split2h(v.x, v.y);
        }
        *(uint32_t*)(psm + r * SROWB + 4 * c2) = p.x;
        *(uint32_t*)(psm + IMG + r * SROWB + 4 * c2) = p.y;
    }
    __syncthreads();

    float* __restrict__ xg = (l == 0) ? g_xg0 : g_xg1;
    const uint4* __restrict__ wf = g_wxf + (size_t)l * 80 * 10 * 32;

#pragma unroll 1
    for (int hf = 0; hf < 2; ++hf) {
        float acc[4][4][4];
#pragma unroll
        for (int u = 0; u < 4; u++)
#pragma unroll
            for (int m = 0; m < 4; m++)
#pragma unroll
                for (int q = 0; q < 4; q++) acc[u][m][q] = 0.f;

#pragma unroll 1
        for (int ks = 0; ks < 10; ++ks) {
            uint32_t Ah[4][4], Al[4][4];
#pragma unroll
            for (int m = 0; m < 4; m++) {
                ldm_x4(Ah[m], smb + (uint32_t)(m * 16 * SROWB + ks * 32) + loff);
                ldm_x4(Al[m], smb + (uint32_t)(IMG + m * 16 * SROWB + ks * 32) + loff);
            }
#pragma unroll
            for (int u = 0; u < 4; ++u) {
                int nt = wid + 10 * (4 * hf + u);
                uint4 B = wf[((size_t)nt * 10 + ks) * 32 + lane];
#pragma unroll
                for (int m = 0; m < 4; m++) {
                    mma_f16(acc[u][m], Ah[m], B.x, B.y);   // Ah*Bh
                    mma_f16(acc[u][m], Al[m], B.x, B.y);   // Al*Bh
                    mma_f16(acc[u][m], Ah[m], B.z, B.w);   // Ah*Bl
                }
            }
        }
        // epilogue: add bias, store fp32 to xg
#pragma unroll
        for (int u = 0; u < 4; ++u) {
            int nt = wid + 10 * (4 * hf + u);
            int n0 = 8 * nt + 2 * tg;
            if (n0 < G4) {
                float2 bias = *(const float2*)(g_bsum + l * NP + n0);
#pragma unroll
                for (int m = 0; m < 4; m++) {
                    int mr0 = m0 + m * 16 + gid;
                    int b0i = mr0 >> 7, t0i = mr0 & 127;
                    float2 v0 = make_float2(acc[u][m][0] + bias.x, acc[u][m][1] + bias.y);
                    *(float2*)(xg + ((size_t)t0i * BB + b0i) * G4 + n0) = v0;
                    int mr1 = mr0 + 8;
                    int b1i = mr1 >> 7, t1i = mr1 & 127;
                    float2 v1 = make_float2(acc[u][m][2] + bias.x, acc[u][m][3] + bias.y);
                    *(float2*)(xg + ((size_t)t1i * BB + b1i) * G4 + n0) = v1;
                }
            }
        }
    }
}

// ---------------- kernel 2: recurrence, 32 rows/block, fused GCN phases ----------------
__global__ __launch_bounds__(320, 2) void recur_mma(
        const float* __restrict__ gw1, const float* __restrict__ gw2,
        float* __restrict__ out) {
    extern __shared__ char smem[];
    const uint32_t smb = smem_u32(smem);
    const int l = blockIdx.y;
    const int r0 = blockIdx.x * 32;
    const int tid = threadIdx.x, lane = tid & 31, wid = tid >> 5;  // 10 warps
    const int gid = lane >> 2, tg = lane & 3;
    const bool evenl = ((lane & 1) == 0);
    const uint32_t loff = (uint32_t)(((lane & 7) + 8 * ((lane >> 3) & 1)) * SROWB + (lane >> 4) * 16);

    for (int i = tid; i < RSMEM2 / 4; i += 320) ((uint32_t*)smem)[i] = 0u;
    __syncthreads();

    uint32_t hH = 0,        hL = IMGR,     cH = 2 * IMGR, cL = 3 * IMGR;
    uint32_t tH = 4 * IMGR, tL = 5 * IMGR, uH = 6 * IMGR, uL = 7 * IMGR;

    const float c1 = gw1[l], c2 = gw2[l];
    const float* __restrict__ xg = (l == 0) ? g_xg0 : g_xg1;
    const uint2* __restrict__ wf = g_wf2 + (size_t)l * 80 * 10 * 32;

    // fused GCN half-step on TWO states: A-state in(aH,aL)->out(oaH,oaL), B-state similarly.
    auto gcn2 = [&](uint32_t aH, uint32_t aL, uint32_t bH, uint32_t bL,
                    uint32_t oaH, uint32_t oaL, uint32_t obH, uint32_t obL,
                    float w, bool rl) {
        float accA[2][2][4], accB[2][2][4];
#pragma unroll
        for (int j = 0; j < 2; j++)
#pragma unroll
            for (int m = 0; m < 2; m++)
#pragma unroll
                for (int q = 0; q < 4; q++) { accA[j][m][q] = 0.f; accB[j][m][q] = 0.f; }
#pragma unroll 1
        for (int ks = 0; ks < 10; ++ks) {
            uint2 B0 = g_adjf2[((size_t)wid * 10 + ks) * 32 + lane];
            uint2 B1 = g_adjf2[((size_t)(wid + 10) * 10 + ks) * 32 + lane];
            uint32_t Fh[2][4], Fl[2][4];
#pragma unroll
            for (int m = 0; m < 2; m++) {
                ldm_x4(Fh[m], smb + aH + (uint32_t)(m * 16 * SROWB + ks * 32) + loff);
                ldm_x4(Fl[m], smb + aL + (uint32_t)(m * 16 * SROWB + ks * 32) + loff);
            }
#pragma unroll
            for (int m = 0; m < 2; m++) {
                mma_f16(accA[0][m], Fh[m], B0.x, B0.y);
                mma_f16(accA[0][m], Fl[m], B0.x, B0.y);
                mma_f16(accA[1][m], Fh[m], B1.x, B1.y);
                mma_f16(accA[1][m], Fl[m], B1.x, B1.y);
            }
#pragma unroll
            for (int m = 0; m < 2; m++) {
                ldm_x4(Fh[m], smb + bH + (uint32_t)(m * 16 * SROWB + ks * 32) + loff);
                ldm_x4(Fl[m], smb + bL + (uint32_t)(m * 16 * SROWB + ks * 32) + loff);
            }
#pragma unroll
            for (int m = 0; m < 2; m++) {
                mma_f16(accB[0][m], Fh[m], B0.x, B0.y);
                mma_f16(accB[0][m], Fl[m], B0.x, B0.y);
                mma_f16(accB[1][m], Fh[m], B1.x, B1.y);
                mma_f16(accB[1][m], Fl[m], B1.x, B1.y);
            }
        }
#pragma unroll
        for (int j = 0; j < 2; j++) {
            int colByte = ((wid + 10 * j) * 8 + 2 * tg) * 2;
#pragma unroll
            for (int m = 0; m < 2; m++) {
                int rb0 = (m * 16 + gid) * SROWB + colByte;
                int rb1 = rb0 + 8 * SROWB;
                {
                    float v0 = w * accA[j][m][0], v1 = w * accA[j][m][1];
                    float v2 = w * accA[j][m][2], v3 = w * accA[j][m][3];
                    if (rl) { v0 = fmaxf(v0, 0.f); v1 = fmaxf(v1, 0.f); v2 = fmaxf(v2, 0.f); v3 = fmaxf(v3, 0.f); }
                    else    { v0 = sigmoidf_(v0);  v1 = sigmoidf_(v1);  v2 = sigmoidf_(v2);  v3 = sigmoidf_(v3); }
                    uint2 p01 = split2h(v0, v1), p23 = split2h(v2, v3);
                    *(uint32_t*)(smem + oaH + rb0) = p01.x;
                    *(uint32_t*)(smem + oaL + rb0) = p01.y;
                    *(uint32_t*)(smem + oaH + rb1) = p23.x;
                    *(uint32_t*)(smem + oaL + rb1) = p23.y;
                }
                {
                    float v0 = w * accB[j][m][0], v1 = w * accB[j][m][1];
                    float v2 = w * accB[j][m][2], v3 = w * accB[j][m][3];
                    if (rl) { v0 = fmaxf(v0, 0.f); v1 = fmaxf(v1, 0.f); v2 = fmaxf(v2, 0.f); v3 = fmaxf(v3, 0.f); }
                    else    { v0 = sigmoidf_(v0);  v1 = sigmoidf_(v1);  v2 = sigmoidf_(v2);  v3 = sigmoidf_(v3); }
                    uint2 p01 = split2h(v0, v1), p23 = split2h(v2, v3);
                    *(uint32_t*)(smem + obH + rb0) = p01.x;
                    *(uint32_t*)(smem + obL + rb0) = p01.y;
                    *(uint32_t*)(smem + obH + rb1) = p23.x;
                    *(uint32_t*)(smem + obL + rb1) = p23.y;
                }
            }
        }
    };

    // gates with xg prefetch: preacts = h @ W^T + xg; cell update in-register
    auto gates = [&](int t) {
#pragma unroll 1
        for (int hf = 0; hf < 2; ++hf) {
            float4 xv[4][2];
#pragma unroll
            for (int u = 0; u < 4; ++u) {
                int nt = wid + 10 * (4 * hf + u);
                int o = 2 * nt + (tg >> 1);
#pragma unroll
                for (int m = 0; m < 2; m++) {
                    int row = m * 16 + gid + (evenl ? 0 : 8);
                    xv[u][m] = (o < HH)
                        ? *(const float4*)(xg + ((size_t)t * BB + (r0 + row)) * G4 + 4 * o)
                        : make_float4(0.f, 0.f, 0.f, 0.f);
                }
            }
            float acc[4][2][4];
#pragma unroll
            for (int u = 0; u < 4; u++)
#pragma unroll
                for (int m = 0; m < 2; m++)
#pragma unroll
                    for (int q = 0; q < 4; q++) acc[u][m][q] = 0.f;
#pragma unroll 1
            for (int ks = 0; ks < 10; ++ks) {
                uint32_t Ah[2][4], Al[2][4];
#pragma unroll
                for (int m = 0; m < 2; m++) {
                    ldm_x4(Ah[m], smb + hH + (uint32_t)(m * 16 * SROWB + ks * 32) + loff);
                    ldm_x4(Al[m], smb + hL + (uint32_t)(m * 16 * SROWB + ks * 32) + loff);
                }
#pragma unroll
                for (int u = 0; u < 4; ++u) {
                    int nt = wid + 10 * (4 * hf + u);
                    uint2 B = wf[((size_t)nt * 10 + ks) * 32 + lane];
#pragma unroll
                    for (int m = 0; m < 2; m++) {
                        mma_f16(acc[u][m], Ah[m], B.x, B.y);
                        mma_f16(acc[u][m], Al[m], B.x, B.y);
                    }
                }
            }
#pragma unroll
            for (int u = 0; u < 4; ++u) {
                int nt = wid + 10 * (4 * hf + u);
                int o = 2 * nt + (tg >> 1);
#pragma unroll
                for (int m = 0; m < 2; m++) {
                    float a0 = acc[u][m][0], a1 = acc[u][m][1];
                    float a2 = acc[u][m][2], a3 = acc[u][m][3];
                    float e0 = __shfl_xor_sync(0xffffffffu, a0, 1);
                    float e1 = __shfl_xor_sync(0xffffffffu, a1, 1);
                    float e2 = __shfl_xor_sync(0xffffffffu, a2, 1);
                    float e3 = __shfl_xor_sync(0xffffffffu, a3, 1);
                    if (o < HH) {
                        int row = m * 16 + gid + (evenl ? 0 : 8);
                        float pi = evenl ? a0 : e2;
                        float pf = evenl ? a1 : e3;
                        float pc = evenl ? e0 : a2;
                        float po = evenl ? e1 : a3;
                        const float4 xvv = xv[u][m];
                        float it = sigmoidf_(pi + xvv.x);
                        float ft = sigmoidf_(pf + xvv.y);
                        float cb = tanhf_fast(pc + xvv.z);
                        float ot = sigmoidf_(po + xvv.w);
                        int sb = row * SROWB + 2 * o;
                        float cold = __half2float(*(__half*)(smem + cH + sb))
                                   + __half2float(*(__half*)(smem + cL + sb));
                        float ct = ft * cold + it * cb;
                        float hn = ot * tanhf_fast(ct);
                        __half cth = __float2half_rn(ct);
                        *(__half*)(smem + cH + sb) = cth;
                        *(__half*)(smem + cL + sb) = __float2half_rn(ct - __half2float(cth));
                        __half hnh = __float2half_rn(hn);
                        *(__half*)(smem + tH + sb) = hnh;
                        *(__half*)(smem + tL + sb) = __float2half_rn(hn - __half2float(hnh));
                        if (l == 1) g_ys[((size_t)(r0 + row) * TT + t) * HH + o] = hn;
                    }
                }
            }
        }
    };

    for (int t = 0; t < TT; ++t) {
        if (t > 0) {
            gcn2(hH, hL, cH, cL, tH, tL, uH, uL, c1, true);  __syncthreads();
            gcn2(tH, tL, uH, uL, hH, hL, cH, cL, c2, false); __syncthreads();
        }
        gates(t);                      // reads h (mma) + c (cold); writes c (ct), T (new h)
        __syncthreads();
        uint32_t s;
        s = hH; hH = tH; tH = s;
        s = hL; hL = tL; tL = s;
    }

    // final states -> h_n, c_n
    constexpr size_t OUT0 = (size_t)BB * OO * HH;
    constexpr size_t HN   = (size_t)LL * BB * HH;
    for (int i = tid; i < 32 * HH; i += 320) {
        int m = i / HH, o = i - m * HH;
        int sb = m * SROWB + 2 * o;
        float hv = __half2float(*(__half*)(smem + hH + sb))
                 + __half2float(*(__half*)(smem + hL + sb));
        float cv = __half2float(*(__half*)(smem + cH + sb))
                 + __half2float(*(__half*)(smem + cL + sb));
        size_t off = ((size_t)l * BB + (r0 + m)) * HH + o;
        out[OUT0 + off]      = hv;
        out[OUT0 + HN + off] = cv;
    }
}

// ---------------- kernel 3: output projection ----------------
constexpr int YROW = TT * HH;  // 19968
constexpr int OSMEM = (YROW + OO * TT + OO) * 4;

__global__ __launch_bounds__(256) void out_kernel(const float* __restrict__ Wout,
                                                  const float* __restrict__ bout,
                                                  float* __restrict__ out) {
    extern __shared__ float sm[];
    float* sy = sm;
    float* sw = sm + YROW;
    float* sb = sw + OO * TT;
    const int b = blockIdx.x;
    const int tid = threadIdx.x;
    const float* yb = g_ys + (size_t)b * YROW;
    for (int i = tid; i < YROW / 4; i += 256) ((float4*)sy)[i] = ((const float4*)yb)[i];
    for (int i = tid; i < OO * TT; i += 256) sw[i] = Wout[i];
    if (tid < OO) sb[tid] = bout[tid];
    __syncthreads();
    for (int idx = tid; idx < HH * OO; idx += 256) {
        int f = idx / OO, jj = idx - f * OO;
        const float* yr = sy + f * TT;
        const float* wr = sw + jj * TT;
        float2 a = make_float2(0.f, 0.f);
#pragma unroll 4
        for (int p = 0; p < TT / 2; ++p)
            a = fma2(a, *(const float2*)(yr + 2 * p), *(const float2*)(wr + 2 * p));
        out[(size_t)b * (HH * OO) + idx] = a.x + a.y + sb[jj];
    }
}

// ---------------- launcher ----------------
extern "C" void kernel_launch(void* const* d_in, const int* in_sizes, int n_in,
                              void* d_out, int out_size) {
    const float* x   = (const float*)d_in[0];
    const float* adj = (const float*)d_in[1];

    XArgs xa;
    xa.W[0] = (const float*)d_in[2];  xa.bx[0] = (const float*)d_in[3];
    xa.W[1] = (const float*)d_in[6];  xa.bx[1] = (const float*)d_in[7];
    xa.W[2] = (const float*)d_in[10]; xa.bx[2] = (const float*)d_in[11];
    xa.W[3] = (const float*)d_in[14]; xa.bx[3] = (const float*)d_in[15];
    xa.bh[0] = (const float*)d_in[5];
    xa.bh[1] = (const float*)d_in[9];
    xa.bh[2] = (const float*)d_in[13];
    xa.bh[3] = (const float*)d_in[17];

    HArgs ha;
    ha.W[0] = (const float*)d_in[4];
    ha.W[1] = (const float*)d_in[8];
    ha.W[2] = (const float*)d_in[12];
    ha.W[3] = (const float*)d_in[16];

    const float* gw1  = (const float*)d_in[18];
    const float* gw2  = (const float*)d_in[19];
    const float* Wout = (const float*)d_in[20];
    const float* bout = (const float*)d_in[21];
    float* out = (float*)d_out;

    cudaFuncSetAttribute(recur_mma,  cudaFuncAttributeMaxDynamicSharedMemorySize, RSMEM2);
    cudaFuncSetAttribute(out_kernel, cudaFuncAttributeMaxDynamicSharedMemorySize, OSMEM);

    setup_bsum <<<(LL * NP + 255) / 256, 256>>>(xa);
    setup_adjf2<<<(20 * 10 * 32 + 255) / 256, 256>>>(adj);
    setup_wf2  <<<(LL * 80 * 10 * 32 + 255) / 256, 256>>>(ha);
    setup_wxf  <<<(LL * 80 * 10 * 32 + 255) / 256, 256>>>(xa);

    dim3 pg(BB * TT / 64, LL);               // 8192 x 2 CTAs
    prelude_hmma<<<pg, 320>>>(x);

    dim3 rg(BB / 32, LL);                    // 128 x 2 = 256 blocks, 2/SM resident
    recur_mma<<<rg, 320, RSMEM2>>>(gw1, gw2, out);

    out_kernel<<<BB, 256, OSMEM>>>(Wout, bout, out);
}

// round 15
// speedup vs baseline: 8.8557x; 1.2718x over previous
#include <cuda_runtime.h>
#include <cuda_bf16.h>
#include <cuda_fp16.h>
#include <cstddef>
#include <cstdint>

// Problem dims
constexpr int BB = 4096;   // batch
constexpr int TT = 128;    // time
constexpr int HH = 156;    // hidden/nodes
constexpr int LL = 2;      // layers
constexpr int OO = 12;     // output len
constexpr int G4 = 4 * HH; // 624  (gate cols, ordered n' = 4*o + g; g: 0=i,1=f,2=c,3=o)
constexpr int NP = 640;    // padded gate width

// Scratch (device globals)
__device__ float g_ys[(size_t)BB * TT * HH];  // ~312 MiB

// Preprocessed data
__device__ float g_bsum[LL * NP];             // bx+bh in n' order
// fragment packs (fp16). adj/h-weights: hi only (uint2). x-weights: hi+lo (uint4).
__device__ uint2 g_adjf2[20 * 10 * 32];       // adj^T fragments
__device__ uint2 g_wf2[LL * 80 * 10 * 32];    // h-weight fragments
__device__ uint4 g_wxf[LL * 80 * 10 * 32];    // x-weight fragments {b0h,b1h,b0l,b1l}

// ---------------- generic helpers ----------------
__device__ __forceinline__ float2 fma2(float2 d, float2 a, float2 b) {
    unsigned long long dd = *reinterpret_cast<unsigned long long*>(&d);
    unsigned long long aa = *reinterpret_cast<unsigned long long*>(&a);
    unsigned long long bb = *reinterpret_cast<unsigned long long*>(&b);
    asm("fma.rn.f32x2 %0, %1, %2, %0;" : "+l"(dd) : "l"(aa), "l"(bb));
    return *reinterpret_cast<float2*>(&dd);
}
__device__ __forceinline__ float sigmoidf_(float x) {
    return __fdividef(1.0f, 1.0f + __expf(-x));
}
__device__ __forceinline__ float tanhf_fast(float x) {
    float ax = fabsf(x);
    float e = __expf(-2.0f * ax);
    float t = __fdividef(1.0f - e, 1.0f + e);
    return copysignf(t, x);
}
__device__ __forceinline__ uint32_t smem_u32(const void* p) {
    uint32_t a;
    asm("{ .reg .u64 t; cvta.to.shared.u64 t, %1; cvt.u32.u64 %0, t; }" : "=r"(a) : "l"(p));
    return a;
}
__device__ __forceinline__ uint32_t packh(float a, float b) {
    __half ha = __float2half_rn(a), hb = __float2half_rn(b);
    return (uint32_t)__half_as_ushort(ha) | ((uint32_t)__half_as_ushort(hb) << 16);
}
// split (x,y) into packed fp16 hi / fp16 lo residual pairs
__device__ __forceinline__ uint2 split2h(float x, float y) {
    __half hx = __float2half_rn(x), hy = __float2half_rn(y);
    float rx = x - __half2float(hx), ry = y - __half2float(hy);
    uint2 r;
    r.x = (uint32_t)__half_as_ushort(hx) | ((uint32_t)__half_as_ushort(hy) << 16);
    r.y = (uint32_t)__half_as_ushort(__float2half_rn(rx)) |
          ((uint32_t)__half_as_ushort(__float2half_rn(ry)) << 16);
    return r;
}
__device__ __forceinline__ void ldm_x4(uint32_t* r, uint32_t addr) {
    asm volatile("ldmatrix.sync.aligned.m8n8.x4.shared.b16 {%0,%1,%2,%3}, [%4];"
                 : "=r"(r[0]), "=r"(r[1]), "=r"(r[2]), "=r"(r[3]) : "r"(addr));
}
__device__ __forceinline__ void mma_f16(float* c, const uint32_t* a, uint32_t b0, uint32_t b1) {
    asm volatile(
        "mma.sync.aligned.m16n8k16.row.col.f32.f16.f16.f32 "
        "{%0,%1,%2,%3}, {%4,%5,%6,%7}, {%8,%9}, {%0,%1,%2,%3};"
        : "+f"(c[0]), "+f"(c[1]), "+f"(c[2]), "+f"(c[3])
        : "r"(a[0]), "r"(a[1]), "r"(a[2]), "r"(a[3]), "r"(b0), "r"(b1));
}

struct XArgs {
    const float* W[4];   // Wix, Wfx, Wcx, Wox   each [L,H,H]
    const float* bx[4];
    const float* bh[4];
};
struct HArgs {
    const float* W[4];   // Wih, Wfh, Wch, Woh  each [L,H,H]
};

// ---------------- setup kernels ----------------
__global__ __launch_bounds__(256) void setup_bsum(XArgs A) {
    int idx = blockIdx.x * 256 + threadIdx.x;
    if (idx >= LL * NP) return;
    int n = idx % NP, l = idx / NP;
    int o = n >> 2, g = n & 3;
    g_bsum[idx] = (o < HH) ? (A.bx[g][l * HH + o] + A.bh[g][l * HH + o]) : 0.f;
}
__global__ __launch_bounds__(256) void setup_adjf2(const float* __restrict__ adj) {
    int idx = blockIdx.x * 256 + threadIdx.x;
    if (idx >= 20 * 10 * 32) return;
    int lane = idx & 31, r = idx >> 5;
    int ks = r % 10, nt = r / 10;
    int gid = lane >> 2, tg = lane & 3;
    int n = nt * 8 + gid;           // output node
    int k0 = ks * 16 + 2 * tg;
    auto val = [&](int k) -> float { return (n < HH && k < HH) ? adj[n * HH + k] : 0.f; };
    g_adjf2[idx] = make_uint2(packh(val(k0), val(k0 + 1)), packh(val(k0 + 8), val(k0 + 9)));
}
__global__ __launch_bounds__(256) void setup_wf2(HArgs A) {
    int idx = blockIdx.x * 256 + threadIdx.x;
    if (idx >= LL * 80 * 10 * 32) return;
    int lane = idx & 31, r = idx >> 5;
    int ks = r % 10; r /= 10;
    int nt = r % 80;
    int l  = r / 80;
    int gid = lane >> 2, tg = lane & 3;
    int np = nt * 8 + gid;          // n' = 4*o + g
    int o = np >> 2, g = np & 3;
    int k0 = ks * 16 + 2 * tg;
    auto val = [&](int k) -> float {
        return (o < HH && k < HH) ? A.W[g][((size_t)l * HH + o) * HH + k] : 0.f;
    };
    g_wf2[idx] = make_uint2(packh(val(k0), val(k0 + 1)), packh(val(k0 + 8), val(k0 + 9)));
}
__global__ __launch_bounds__(256) void setup_wxf(XArgs A) {
    int idx = blockIdx.x * 256 + threadIdx.x;
    if (idx >= LL * 80 * 10 * 32) return;
    int lane = idx & 31, r = idx >> 5;
    int ks = r % 10; r /= 10;
    int nt = r % 80;
    int l  = r / 80;
    int gid = lane >> 2, tg = lane & 3;
    int np = nt * 8 + gid;          // n' = 4*o + g
    int o = np >> 2, g = np & 3;
    int k0 = ks * 16 + 2 * tg;
    auto val = [&](int k) -> float {
        return (o < HH && k < HH) ? A.W[g][((size_t)l * HH + o) * HH + k] : 0.f;
    };
    float v0 = val(k0), v1 = val(k0 + 1), v2 = val(k0 + 8), v3 = val(k0 + 9);
    uint2 p0 = split2h(v0, v1);
    uint2 p1 = split2h(v2, v3);
    g_wxf[idx] = make_uint4(p0.x, p1.x, p0.y, p1.y);
}

// ---------------- shared layout constants ----------------
constexpr int SROWB = 336;                 // image row stride in bytes (168 fp16)
constexpr int IMGR = 32 * SROWB;           // 32-row image = 10752 B
constexpr int SM_BIAS = 10 * IMGR;         // bias floats after 10 images
constexpr int RSMEM2 = SM_BIAS + NP * 4;   // 110080 B

// ---------------- the one big kernel: recurrence with fused x@Wx (prelude folded in) ----------------
__global__ __launch_bounds__(320, 2) void recur_mma(
        const float* __restrict__ x,
        const float* __restrict__ gw1, const float* __restrict__ gw2,
        float* __restrict__ out) {
    extern __shared__ char smem[];
    const uint32_t smb = smem_u32(smem);
    float* sbias = (float*)(smem + SM_BIAS);
    const int l = blockIdx.y;
    const int r0 = blockIdx.x * 32;
    const int tid = threadIdx.x, lane = tid & 31, wid = tid >> 5;  // 10 warps
    const int gid = lane >> 2, tg = lane & 3;
    const bool evenl = ((lane & 1) == 0);
    const uint32_t loff = (uint32_t)(((lane & 7) + 8 * ((lane >> 3) & 1)) * SROWB + (lane >> 4) * 16);

    for (int i = tid; i < (10 * IMGR) / 4; i += 320) ((uint32_t*)smem)[i] = 0u;
    for (int i = tid; i < NP; i += 320) sbias[i] = g_bsum[l * NP + i];
    __syncthreads();

    uint32_t hH = 0,        hL = IMGR,     cH = 2 * IMGR, cL = 3 * IMGR;
    uint32_t tH = 4 * IMGR, tL = 5 * IMGR, uH = 6 * IMGR, uL = 7 * IMGR;
    const uint32_t xH = 8 * IMGR, xL = 9 * IMGR;

    const float c1 = gw1[l], c2 = gw2[l];
    const uint2* __restrict__ wf  = g_wf2 + (size_t)l * 80 * 10 * 32;
    const uint4* __restrict__ wxf = g_wxf + (size_t)l * 80 * 10 * 32;

    // ---- x staging: prefetch 32x156 fp32 into regs (4 x float4/thread) ----
    float4 xv4[4];
    int xr_[4], xc_[4];
    auto xfetch = [&](int t) {
#pragma unroll
        for (int i = 0; i < 4; ++i) {
            int idx = tid + 320 * i;            // 0..1279, need 32*39=1248
            if (idx < 32 * 39) {
                int r = idx / 39, c4 = idx % 39;
                xr_[i] = r; xc_[i] = c4;
                xv4[i] = *(const float4*)(x + ((size_t)(r0 + r) * TT + t) * HH + 4 * c4);
            } else { xr_[i] = -1; xc_[i] = 0; xv4[i] = make_float4(0.f, 0.f, 0.f, 0.f); }
        }
    };
    auto xstore = [&]() {
#pragma unroll
        for (int i = 0; i < 4; ++i) {
            if (xr_[i] >= 0) {
                uint2 p01 = split2h(xv4[i].x, xv4[i].y);
                uint2 p23 = split2h(xv4[i].z, xv4[i].w);
                int sb = xr_[i] * SROWB + 8 * xc_[i];
                *(uint2*)(smem + xH + sb) = make_uint2(p01.x, p23.x);
                *(uint2*)(smem + xL + sb) = make_uint2(p01.y, p23.y);
            }
        }
    };

    // fused GCN half-step on TWO states
    auto gcn2 = [&](uint32_t aH, uint32_t aL, uint32_t bH, uint32_t bL,
                    uint32_t oaH, uint32_t oaL, uint32_t obH, uint32_t obL,
                    float w, bool rl) {
        float accA[2][2][4], accB[2][2][4];
#pragma unroll
        for (int j = 0; j < 2; j++)
#pragma unroll
            for (int m = 0; m < 2; m++)
#pragma unroll
                for (int q = 0; q < 4; q++) { accA[j][m][q] = 0.f; accB[j][m][q] = 0.f; }
#pragma unroll 1
        for (int ks = 0; ks < 10; ++ks) {
            uint2 B0 = g_adjf2[((size_t)wid * 10 + ks) * 32 + lane];
            uint2 B1 = g_adjf2[((size_t)(wid + 10) * 10 + ks) * 32 + lane];
            uint32_t Fh[2][4], Fl[2][4];
#pragma unroll
            for (int m = 0; m < 2; m++) {
                ldm_x4(Fh[m], smb + aH + (uint32_t)(m * 16 * SROWB + ks * 32) + loff);
                ldm_x4(Fl[m], smb + aL + (uint32_t)(m * 16 * SROWB + ks * 32) + loff);
            }
#pragma unroll
            for (int m = 0; m < 2; m++) {
                mma_f16(accA[0][m], Fh[m], B0.x, B0.y);
                mma_f16(accA[0][m], Fl[m], B0.x, B0.y);
                mma_f16(accA[1][m], Fh[m], B1.x, B1.y);
                mma_f16(accA[1][m], Fl[m], B1.x, B1.y);
            }
#pragma unroll
            for (int m = 0; m < 2; m++) {
                ldm_x4(Fh[m], smb + bH + (uint32_t)(m * 16 * SROWB + ks * 32) + loff);
                ldm_x4(Fl[m], smb + bL + (uint32_t)(m * 16 * SROWB + ks * 32) + loff);
            }
#pragma unroll
            for (int m = 0; m < 2; m++) {
                mma_f16(accB[0][m], Fh[m], B0.x, B0.y);
                mma_f16(accB[0][m], Fl[m], B0.x, B0.y);
                mma_f16(accB[1][m], Fh[m], B1.x, B1.y);
                mma_f16(accB[1][m], Fl[m], B1.x, B1.y);
            }
        }
#pragma unroll
        for (int j = 0; j < 2; j++) {
            int colByte = ((wid + 10 * j) * 8 + 2 * tg) * 2;
#pragma unroll
            for (int m = 0; m < 2; m++) {
                int rb0 = (m * 16 + gid) * SROWB + colByte;
                int rb1 = rb0 + 8 * SROWB;
                {
                    float v0 = w * accA[j][m][0], v1 = w * accA[j][m][1];
                    float v2 = w * accA[j][m][2], v3 = w * accA[j][m][3];
                    if (rl) { v0 = fmaxf(v0, 0.f); v1 = fmaxf(v1, 0.f); v2 = fmaxf(v2, 0.f); v3 = fmaxf(v3, 0.f); }
                    else    { v0 = sigmoidf_(v0);  v1 = sigmoidf_(v1);  v2 = sigmoidf_(v2);  v3 = sigmoidf_(v3); }
                    uint2 p01 = split2h(v0, v1), p23 = split2h(v2, v3);
                    *(uint32_t*)(smem + oaH + rb0) = p01.x;
                    *(uint32_t*)(smem + oaL + rb0) = p01.y;
                    *(uint32_t*)(smem + oaH + rb1) = p23.x;
                    *(uint32_t*)(smem + oaL + rb1) = p23.y;
                }
                {
                    float v0 = w * accB[j][m][0], v1 = w * accB[j][m][1];
                    float v2 = w * accB[j][m][2], v3 = w * accB[j][m][3];
                    if (rl) { v0 = fmaxf(v0, 0.f); v1 = fmaxf(v1, 0.f); v2 = fmaxf(v2, 0.f); v3 = fmaxf(v3, 0.f); }
                    else    { v0 = sigmoidf_(v0);  v1 = sigmoidf_(v1);  v2 = sigmoidf_(v2);  v3 = sigmoidf_(v3); }
                    uint2 p01 = split2h(v0, v1), p23 = split2h(v2, v3);
                    *(uint32_t*)(smem + obH + rb0) = p01.x;
                    *(uint32_t*)(smem + obL + rb0) = p01.y;
                    *(uint32_t*)(smem + obH + rb1) = p23.x;
                    *(uint32_t*)(smem + obL + rb1) = p23.y;
                }
            }
        }
    };

    // gates: preacts = h @ Wh^T + x_t @ Wx^T + bias (n' = 4o+g cols); cell update in-register
    auto gates = [&](int t) {
#pragma unroll 1
        for (int hf = 0; hf < 2; ++hf) {
            float acc[4][2][4];
#pragma unroll
            for (int u = 0; u < 4; u++)
#pragma unroll
                for (int m = 0; m < 2; m++)
#pragma unroll
                    for (int q = 0; q < 4; q++) acc[u][m][q] = 0.f;
            // K-loop 1: h-side (fp16x2)
#pragma unroll 1
            for (int ks = 0; ks < 10; ++ks) {
                uint32_t Ah[2][4], Al[2][4];
#pragma unroll
                for (int m = 0; m < 2; m++) {
                    ldm_x4(Ah[m], smb + hH + (uint32_t)(m * 16 * SROWB + ks * 32) + loff);
                    ldm_x4(Al[m], smb + hL + (uint32_t)(m * 16 * SROWB + ks * 32) + loff);
                }
#pragma unroll
                for (int u = 0; u < 4; ++u) {
                    int nt = wid + 10 * (4 * hf + u);
                    uint2 B = wf[((size_t)nt * 10 + ks) * 32 + lane];
#pragma unroll
                    for (int m = 0; m < 2; m++) {
                        mma_f16(acc[u][m], Ah[m], B.x, B.y);
                        mma_f16(acc[u][m], Al[m], B.x, B.y);
                    }
                }
            }
            // K-loop 2: x-side (fp16x3, fused former prelude)
#pragma unroll 1
            for (int ks = 0; ks < 10; ++ks) {
                uint32_t Ah[2][4], Al[2][4];
#pragma unroll
                for (int m = 0; m < 2; m++) {
                    ldm_x4(Ah[m], smb + xH + (uint32_t)(m * 16 * SROWB + ks * 32) + loff);
                    ldm_x4(Al[m], smb + xL + (uint32_t)(m * 16 * SROWB + ks * 32) + loff);
                }
#pragma unroll
                for (int u = 0; u < 4; ++u) {
                    int nt = wid + 10 * (4 * hf + u);
                    uint4 B = wxf[((size_t)nt * 10 + ks) * 32 + lane];
#pragma unroll
                    for (int m = 0; m < 2; m++) {
                        mma_f16(acc[u][m], Ah[m], B.x, B.y);   // xh*Wh
                        mma_f16(acc[u][m], Al[m], B.x, B.y);   // xl*Wh
                        mma_f16(acc[u][m], Ah[m], B.z, B.w);   // xh*Wl
                    }
                }
            }
#pragma unroll
            for (int u = 0; u < 4; ++u) {
                int nt = wid + 10 * (4 * hf + u);
                int o = 2 * nt + (tg >> 1);
#pragma unroll
                for (int m = 0; m < 2; m++) {
                    float a0 = acc[u][m][0], a1 = acc[u][m][1];
                    float a2 = acc[u][m][2], a3 = acc[u][m][3];
                    float e0 = __shfl_xor_sync(0xffffffffu, a0, 1);
                    float e1 = __shfl_xor_sync(0xffffffffu, a1, 1);
                    float e2 = __shfl_xor_sync(0xffffffffu, a2, 1);
                    float e3 = __shfl_xor_sync(0xffffffffu, a3, 1);
                    if (o < HH) {
                        int row = m * 16 + gid + (evenl ? 0 : 8);
                        float pi = evenl ? a0 : e2;
                        float pf = evenl ? a1 : e3;
                        float pc = evenl ? e0 : a2;
                        float po = evenl ? e1 : a3;
                        const float4 bv = *(const float4*)(sbias + 4 * o);
                        float it = sigmoidf_(pi + bv.x);
                        float ft = sigmoidf_(pf + bv.y);
                        float cb = tanhf_fast(pc + bv.z);
                        float ot = sigmoidf_(po + bv.w);
                        int sb = row * SROWB + 2 * o;
                        float cold = __half2float(*(__half*)(smem + cH + sb))
                                   + __half2float(*(__half*)(smem + cL + sb));
                        float ct = ft * cold + it * cb;
                        float hn = ot * tanhf_fast(ct);
                        __half cth = __float2half_rn(ct);
                        *(__half*)(smem + cH + sb) = cth;
                        *(__half*)(smem + cL + sb) = __float2half_rn(ct - __half2float(cth));
                        __half hnh = __float2half_rn(hn);
                        *(__half*)(smem + tH + sb) = hnh;
                        *(__half*)(smem + tL + sb) = __float2half_rn(hn - __half2float(hnh));
                        if (l == 1) g_ys[((size_t)(r0 + row) * TT + t) * HH + o] = hn;
                    }
                }
            }
        }
    };

    // stage x_0
    xfetch(0); xstore();
    __syncthreads();

    for (int t = 0; t < TT; ++t) {
        if (t > 0) {
            xfetch(t);                                       // LDGs issue, drain behind gcn mma
            gcn2(hH, hL, cH, cL, tH, tL, uH, uL, c1, true);
            xstore();                                        // x_t image ready before barrier
            __syncthreads();
            gcn2(tH, tL, uH, uL, hH, hL, cH, cL, c2, false); __syncthreads();
        }
        gates(t);                      // reads h,x (mma) + c (cold); writes c (ct), T (new h)
        __syncthreads();
        uint32_t s;
        s = hH; hH = tH; tH = s;
        s = hL; hL = tL; tL = s;
    }

    // final states -> h_n, c_n
    constexpr size_t OUT0 = (size_t)BB * OO * HH;
    constexpr size_t HN   = (size_t)LL * BB * HH;
    for (int i = tid; i < 32 * HH; i += 320) {
        int m = i / HH, o = i - m * HH;
        int sb = m * SROWB + 2 * o;
        float hv = __half2float(*(__half*)(smem + hH + sb))
                 + __half2float(*(__half*)(smem + hL + sb));
        float cv = __half2float(*(__half*)(smem + cH + sb))
                 + __half2float(*(__half*)(smem + cL + sb));
        size_t off = ((size_t)l * BB + (r0 + m)) * HH + o;
        out[OUT0 + off]      = hv;
        out[OUT0 + HN + off] = cv;
    }
}

// ---------------- kernel 3: output projection ----------------
constexpr int YROW = TT * HH;  // 19968
constexpr int OSMEM = (YROW + OO * TT + OO) * 4;

__global__ __launch_bounds__(256) void out_kernel(const float* __restrict__ Wout,
                                                  const float* __restrict__ bout,
                                                  float* __restrict__ out) {
    extern __shared__ float sm[];
    float* sy = sm;
    float* sw = sm + YROW;
    float* sb = sw + OO * TT;
    const int b = blockIdx.x;
    const int tid = threadIdx.x;
    const float* yb = g_ys + (size_t)b * YROW;
    for (int i = tid; i < YROW / 4; i += 256) ((float4*)sy)[i] = ((const float4*)yb)[i];
    for (int i = tid; i < OO * TT; i += 256) sw[i] = Wout[i];
    if (tid < OO) sb[tid] = bout[tid];
    __syncthreads();
    for (int idx = tid; idx < HH * OO; idx += 256) {
        int f = idx / OO, jj = idx - f * OO;
        const float* yr = sy + f * TT;
        const float* wr = sw + jj * TT;
        float2 a = make_float2(0.f, 0.f);
#pragma unroll 4
        for (int p = 0; p < TT / 2; ++p)
            a = fma2(a, *(const float2*)(yr + 2 * p), *(const float2*)(wr + 2 * p));
        out[(size_t)b * (HH * OO) + idx] = a.x + a.y + sb[jj];
    }
}

// ---------------- launcher ----------------
extern "C" void kernel_launch(void* const* d_in, const int* in_sizes, int n_in,
                              void* d_out, int out_size) {
    const float* x   = (const float*)d_in[0];
    const float* adj = (const float*)d_in[1];

    XArgs xa;
    xa.W[0] = (const float*)d_in[2];  xa.bx[0] = (const float*)d_in[3];
    xa.W[1] = (const float*)d_in[6];  xa.bx[1] = (const float*)d_in[7];
    xa.W[2] = (const float*)d_in[10]; xa.bx[2] = (const float*)d_in[11];
    xa.W[3] = (const float*)d_in[14]; xa.bx[3] = (const float*)d_in[15];
    xa.bh[0] = (const float*)d_in[5];
    xa.bh[1] = (const float*)d_in[9];
    xa.bh[2] = (const float*)d_in[13];
    xa.bh[3] = (const float*)d_in[17];

    HArgs ha;
    ha.W[0] = (const float*)d_in[4];
    ha.W[1] = (const float*)d_in[8];
    ha.W[2] = (const float*)d_in[12];
    ha.W[3] = (const float*)d_in[16];

    const float* gw1  = (const float*)d_in[18];
    const float* gw2  = (const float*)d_in[19];
    const float* Wout = (const float*)d_in[20];
    const float* bout = (const float*)d_in[21];
    float* out = (float*)d_out;

    cudaFuncSetAttribute(recur_mma,  cudaFuncAttributeMaxDynamicSharedMemorySize, RSMEM2);
    cudaFuncSetAttribute(out_kernel, cudaFuncAttributeMaxDynamicSharedMemorySize, OSMEM);

    setup_bsum <<<(LL * NP + 255) / 256, 256>>>(xa);
    setup_adjf2<<<(20 * 10 * 32 + 255) / 256, 256>>>(adj);
    setup_wf2  <<<(LL * 80 * 10 * 32 + 255) / 256, 256>>>(ha);
    setup_wxf  <<<(LL * 80 * 10 * 32 + 255) / 256, 256>>>(xa);

    dim3 rg(BB / 32, LL);                    // 128 x 2 = 256 blocks, 2/SM resident
    recur_mma<<<rg, 320, RSMEM2>>>(x, gw1, gw2, out);

    out_kernel<<<BB, 256, OSMEM>>>(Wout, bout, out);
}

// round 16
// speedup vs baseline: 13.8107x; 1.5595x over previous
#include <cuda_runtime.h>
#include <cuda_bf16.h>
#include <cuda_fp16.h>
#include <cstddef>
#include <cstdint>

// Problem dims
constexpr int BB = 4096;   // batch
constexpr int TT = 128;    // time
constexpr int HH = 156;    // hidden/nodes
constexpr int LL = 2;      // layers
constexpr int OO = 12;     // output len
constexpr int G4 = 4 * HH; // 624  (gate cols, ordered n' = 4*o + g; g: 0=i,1=f,2=c,3=o)
constexpr int NP = 640;    // padded gate width

// Scratch (device globals)
__device__ float g_ys[(size_t)BB * TT * HH];  // ~312 MiB

// Preprocessed data
__device__ float g_bsum[LL * NP];             // bx+bh in n' order
// fragment packs (single fp16): {b0, b1} per (n-tile, k-step, lane)
__device__ uint2 g_adjf2[20 * 10 * 32];       // adj^T fragments
__device__ uint2 g_wf2[LL * 80 * 10 * 32];    // h-weight fragments
__device__ uint2 g_wxf2[LL * 80 * 10 * 32];   // x-weight fragments

// ---------------- generic helpers ----------------
__device__ __forceinline__ float2 fma2(float2 d, float2 a, float2 b) {
    unsigned long long dd = *reinterpret_cast<unsigned long long*>(&d);
    unsigned long long aa = *reinterpret_cast<unsigned long long*>(&a);
    unsigned long long bb = *reinterpret_cast<unsigned long long*>(&b);
    asm("fma.rn.f32x2 %0, %1, %2, %0;" : "+l"(dd) : "l"(aa), "l"(bb));
    return *reinterpret_cast<float2*>(&dd);
}
__device__ __forceinline__ float sigmoidf_(float x) {
    return __fdividef(1.0f, 1.0f + __expf(-x));
}
__device__ __forceinline__ float tanhf_fast(float x) {
    float ax = fabsf(x);
    float e = __expf(-2.0f * ax);
    float t = __fdividef(1.0f - e, 1.0f + e);
    return copysignf(t, x);
}
__device__ __forceinline__ uint32_t smem_u32(const void* p) {
    uint32_t a;
    asm("{ .reg .u64 t; cvta.to.shared.u64 t, %1; cvt.u32.u64 %0, t; }" : "=r"(a) : "l"(p));
    return a;
}
__device__ __forceinline__ uint32_t packh(float a, float b) {
    __half ha = __float2half_rn(a), hb = __float2half_rn(b);
    return (uint32_t)__half_as_ushort(ha) | ((uint32_t)__half_as_ushort(hb) << 16);
}
__device__ __forceinline__ void ldm_x4(uint32_t* r, uint32_t addr) {
    asm volatile("ldmatrix.sync.aligned.m8n8.x4.shared.b16 {%0,%1,%2,%3}, [%4];"
                 : "=r"(r[0]), "=r"(r[1]), "=r"(r[2]), "=r"(r[3]) : "r"(addr));
}
__device__ __forceinline__ void mma_f16(float* c, const uint32_t* a, uint32_t b0, uint32_t b1) {
    asm volatile(
        "mma.sync.aligned.m16n8k16.row.col.f32.f16.f16.f32 "
        "{%0,%1,%2,%3}, {%4,%5,%6,%7}, {%8,%9}, {%0,%1,%2,%3};"
        : "+f"(c[0]), "+f"(c[1]), "+f"(c[2]), "+f"(c[3])
        : "r"(a[0]), "r"(a[1]), "r"(a[2]), "r"(a[3]), "r"(b0), "r"(b1));
}

struct XArgs {
    const float* W[4];   // Wix, Wfx, Wcx, Wox   each [L,H,H]
    const float* bx[4];
    const float* bh[4];
};
struct HArgs {
    const float* W[4];   // Wih, Wfh, Wch, Woh  each [L,H,H]
};

// ---------------- setup kernels ----------------
__global__ __launch_bounds__(256) void setup_bsum(XArgs A) {
    int idx = blockIdx.x * 256 + threadIdx.x;
    if (idx >= LL * NP) return;
    int n = idx % NP, l = idx / NP;
    int o = n >> 2, g = n & 3;
    g_bsum[idx] = (o < HH) ? (A.bx[g][l * HH + o] + A.bh[g][l * HH + o]) : 0.f;
}
__global__ __launch_bounds__(256) void setup_adjf2(const float* __restrict__ adj) {
    int idx = blockIdx.x * 256 + threadIdx.x;
    if (idx >= 20 * 10 * 32) return;
    int lane = idx & 31, r = idx >> 5;
    int ks = r % 10, nt = r / 10;
    int gid = lane >> 2, tg = lane & 3;
    int n = nt * 8 + gid;           // output node
    int k0 = ks * 16 + 2 * tg;
    auto val = [&](int k) -> float { return (n < HH && k < HH) ? adj[n * HH + k] : 0.f; };
    g_adjf2[idx] = make_uint2(packh(val(k0), val(k0 + 1)), packh(val(k0 + 8), val(k0 + 9)));
}
__global__ __launch_bounds__(256) void setup_wf2(HArgs A) {
    int idx = blockIdx.x * 256 + threadIdx.x;
    if (idx >= LL * 80 * 10 * 32) return;
    int lane = idx & 31, r = idx >> 5;
    int ks = r % 10; r /= 10;
    int nt = r % 80;
    int l  = r / 80;
    int gid = lane >> 2, tg = lane & 3;
    int np = nt * 8 + gid;          // n' = 4*o + g
    int o = np >> 2, g = np & 3;
    int k0 = ks * 16 + 2 * tg;
    auto val = [&](int k) -> float {
        return (o < HH && k < HH) ? A.W[g][((size_t)l * HH + o) * HH + k] : 0.f;
    };
    g_wf2[idx] = make_uint2(packh(val(k0), val(k0 + 1)), packh(val(k0 + 8), val(k0 + 9)));
}
__global__ __launch_bounds__(256) void setup_wxf2(XArgs A) {
    int idx = blockIdx.x * 256 + threadIdx.x;
    if (idx >= LL * 80 * 10 * 32) return;
    int lane = idx & 31, r = idx >> 5;
    int ks = r % 10; r /= 10;
    int nt = r % 80;
    int l  = r / 80;
    int gid = lane >> 2, tg = lane & 3;
    int np = nt * 8 + gid;          // n' = 4*o + g
    int o = np >> 2, g = np & 3;
    int k0 = ks * 16 + 2 * tg;
    auto val = [&](int k) -> float {
        return (o < HH && k < HH) ? A.W[g][((size_t)l * HH + o) * HH + k] : 0.f;
    };
    g_wxf2[idx] = make_uint2(packh(val(k0), val(k0 + 1)), packh(val(k0 + 8), val(k0 + 9)));
}

// ---------------- shared layout constants ----------------
constexpr int SROWB = 336;                 // image row stride in bytes (168 fp16)
constexpr int IMGR = 32 * SROWB;           // 32-row image = 10752 B
constexpr int SM_BIAS = 5 * IMGR;          // bias floats after 5 images (h,c,t,u,x)
constexpr int RSMEM2 = SM_BIAS + NP * 4;   // 56320 B

// ---------------- the one big kernel: recurrence with fused x@Wx ----------------
__global__ __launch_bounds__(320, 2) void recur_mma(
        const float* __restrict__ x,
        const float* __restrict__ gw1, const float* __restrict__ gw2,
        float* __restrict__ out) {
    extern __shared__ char smem[];
    const uint32_t smb = smem_u32(smem);
    float* sbias = (float*)(smem + SM_BIAS);
    const int l = blockIdx.y;
    const int r0 = blockIdx.x * 32;
    const int tid = threadIdx.x, lane = tid & 31, wid = tid >> 5;  // 10 warps
    const int gid = lane >> 2, tg = lane & 3;
    const bool evenl = ((lane & 1) == 0);
    const uint32_t loff = (uint32_t)(((lane & 7) + 8 * ((lane >> 3) & 1)) * SROWB + (lane >> 4) * 16);

    for (int i = tid; i < (5 * IMGR) / 4; i += 320) ((uint32_t*)smem)[i] = 0u;
    for (int i = tid; i < NP; i += 320) sbias[i] = g_bsum[l * NP + i];
    __syncthreads();

    uint32_t hI = 0, cI = IMGR, tI = 2 * IMGR, uI = 3 * IMGR;
    const uint32_t xI = 4 * IMGR;

    const float c1 = gw1[l], c2 = gw2[l];
    const uint2* __restrict__ wf  = g_wf2  + (size_t)l * 80 * 10 * 32;
    const uint2* __restrict__ wxf = g_wxf2 + (size_t)l * 80 * 10 * 32;

    // ---- x staging: prefetch 32x156 fp32 into regs (4 x float4/thread) ----
    float4 xv4[4];
    int xr_[4], xc_[4];
    auto xfetch = [&](int t) {
#pragma unroll
        for (int i = 0; i < 4; ++i) {
            int idx = tid + 320 * i;            // 0..1279, need 32*39=1248
            if (idx < 32 * 39) {
                int r = idx / 39, c4 = idx % 39;
                xr_[i] = r; xc_[i] = c4;
                xv4[i] = *(const float4*)(x + ((size_t)(r0 + r) * TT + t) * HH + 4 * c4);
            } else { xr_[i] = -1; xc_[i] = 0; xv4[i] = make_float4(0.f, 0.f, 0.f, 0.f); }
        }
    };
    auto xstore = [&]() {
#pragma unroll
        for (int i = 0; i < 4; ++i) {
            if (xr_[i] >= 0) {
                uint2 p = make_uint2(packh(xv4[i].x, xv4[i].y), packh(xv4[i].z, xv4[i].w));
                *(uint2*)(smem + xI + xr_[i] * SROWB + 8 * xc_[i]) = p;
            }
        }
    };

    // fused GCN half-step on TWO states (single fp16 images)
    auto gcn2 = [&](uint32_t aI, uint32_t bI, uint32_t oaI, uint32_t obI,
                    float w, bool rl) {
        float accA[2][2][4], accB[2][2][4];
#pragma unroll
        for (int j = 0; j < 2; j++)
#pragma unroll
            for (int m = 0; m < 2; m++)
#pragma unroll
                for (int q = 0; q < 4; q++) { accA[j][m][q] = 0.f; accB[j][m][q] = 0.f; }
#pragma unroll 1
        for (int ks = 0; ks < 10; ++ks) {
            uint2 B0 = g_adjf2[((size_t)wid * 10 + ks) * 32 + lane];
            uint2 B1 = g_adjf2[((size_t)(wid + 10) * 10 + ks) * 32 + lane];
            uint32_t Fa[2][4], Fb[2][4];
#pragma unroll
            for (int m = 0; m < 2; m++) {
                ldm_x4(Fa[m], smb + aI + (uint32_t)(m * 16 * SROWB + ks * 32) + loff);
                ldm_x4(Fb[m], smb + bI + (uint32_t)(m * 16 * SROWB + ks * 32) + loff);
            }
#pragma unroll
            for (int m = 0; m < 2; m++) {
                mma_f16(accA[0][m], Fa[m], B0.x, B0.y);
                mma_f16(accA[1][m], Fa[m], B1.x, B1.y);
                mma_f16(accB[0][m], Fb[m], B0.x, B0.y);
                mma_f16(accB[1][m], Fb[m], B1.x, B1.y);
            }
        }
#pragma unroll
        for (int j = 0; j < 2; j++) {
            int colByte = ((wid + 10 * j) * 8 + 2 * tg) * 2;
#pragma unroll
            for (int m = 0; m < 2; m++) {
                int rb0 = (m * 16 + gid) * SROWB + colByte;
                int rb1 = rb0 + 8 * SROWB;
                {
                    float v0 = w * accA[j][m][0], v1 = w * accA[j][m][1];
                    float v2 = w * accA[j][m][2], v3 = w * accA[j][m][3];
                    if (rl) { v0 = fmaxf(v0, 0.f); v1 = fmaxf(v1, 0.f); v2 = fmaxf(v2, 0.f); v3 = fmaxf(v3, 0.f); }
                    else    { v0 = sigmoidf_(v0);  v1 = sigmoidf_(v1);  v2 = sigmoidf_(v2);  v3 = sigmoidf_(v3); }
                    *(uint32_t*)(smem + oaI + rb0) = packh(v0, v1);
                    *(uint32_t*)(smem + oaI + rb1) = packh(v2, v3);
                }
                {
                    float v0 = w * accB[j][m][0], v1 = w * accB[j][m][1];
                    float v2 = w * accB[j][m][2], v3 = w * accB[j][m][3];
                    if (rl) { v0 = fmaxf(v0, 0.f); v1 = fmaxf(v1, 0.f); v2 = fmaxf(v2, 0.f); v3 = fmaxf(v3, 0.f); }
                    else    { v0 = sigmoidf_(v0);  v1 = sigmoidf_(v1);  v2 = sigmoidf_(v2);  v3 = sigmoidf_(v3); }
                    *(uint32_t*)(smem + obI + rb0) = packh(v0, v1);
                    *(uint32_t*)(smem + obI + rb1) = packh(v2, v3);
                }
            }
        }
    };

    // gates: preacts = h @ Wh^T + x_t @ Wx^T + bias (n' = 4o+g); cell update in-register
    auto gates = [&](int t) {
#pragma unroll 1
        for (int hf = 0; hf < 2; ++hf) {
            float acc[4][2][4];
#pragma unroll
            for (int u = 0; u < 4; u++)
#pragma unroll
                for (int m = 0; m < 2; m++)
#pragma unroll
                    for (int q = 0; q < 4; q++) acc[u][m][q] = 0.f;
            // merged K-loop: h-side + x-side (both single fp16)
#pragma unroll 1
            for (int ks = 0; ks < 10; ++ks) {
                uint32_t Ah[2][4], Ax[2][4];
#pragma unroll
                for (int m = 0; m < 2; m++) {
                    ldm_x4(Ah[m], smb + hI + (uint32_t)(m * 16 * SROWB + ks * 32) + loff);
                    ldm_x4(Ax[m], smb + xI + (uint32_t)(m * 16 * SROWB + ks * 32) + loff);
                }
#pragma unroll
                for (int u = 0; u < 4; ++u) {
                    int nt = wid + 10 * (4 * hf + u);
                    uint2 Bh = wf[((size_t)nt * 10 + ks) * 32 + lane];
                    uint2 Bx = wxf[((size_t)nt * 10 + ks) * 32 + lane];
#pragma unroll
                    for (int m = 0; m < 2; m++) {
                        mma_f16(acc[u][m], Ah[m], Bh.x, Bh.y);
                        mma_f16(acc[u][m], Ax[m], Bx.x, Bx.y);
                    }
                }
            }
#pragma unroll
            for (int u = 0; u < 4; ++u) {
                int nt = wid + 10 * (4 * hf + u);
                int o = 2 * nt + (tg >> 1);
#pragma unroll
                for (int m = 0; m < 2; m++) {
                    float a0 = acc[u][m][0], a1 = acc[u][m][1];
                    float a2 = acc[u][m][2], a3 = acc[u][m][3];
                    float e0 = __shfl_xor_sync(0xffffffffu, a0, 1);
                    float e1 = __shfl_xor_sync(0xffffffffu, a1, 1);
                    float e2 = __shfl_xor_sync(0xffffffffu, a2, 1);
                    float e3 = __shfl_xor_sync(0xffffffffu, a3, 1);
                    if (o < HH) {
                        int row = m * 16 + gid + (evenl ? 0 : 8);
                        float pi = evenl ? a0 : e2;
                        float pf = evenl ? a1 : e3;
                        float pc = evenl ? e0 : a2;
                        float po = evenl ? e1 : a3;
                        const float4 bv = *(const float4*)(sbias + 4 * o);
                        float it = sigmoidf_(pi + bv.x);
                        float ft = sigmoidf_(pf + bv.y);
                        float cb = tanhf_fast(pc + bv.z);
                        float ot = sigmoidf_(po + bv.w);
                        int sb = row * SROWB + 2 * o;
                        float cold = __half2float(*(__half*)(smem + cI + sb));
                        float ct = ft * cold + it * cb;
                        float hn = ot * tanhf_fast(ct);
                        *(__half*)(smem + cI + sb) = __float2half_rn(ct);
                        *(__half*)(smem + tI + sb) = __float2half_rn(hn);
                        if (l == 1) g_ys[((size_t)(r0 + row) * TT + t) * HH + o] = hn;
                    }
                }
            }
        }
    };

    // stage x_0
    xfetch(0); xstore();
    __syncthreads();

    for (int t = 0; t < TT; ++t) {
        if (t > 0) {
            xfetch(t);                                 // LDGs issue, drain behind gcn mma
            gcn2(hI, cI, tI, uI, c1, true);
            xstore();                                  // x_t image ready before barrier
            __syncthreads();
            gcn2(tI, uI, hI, cI, c2, false); __syncthreads();
        }
        gates(t);                      // reads h,x (mma) + c (cold); writes c (ct), T (new h)
        __syncthreads();
        uint32_t s = hI; hI = tI; tI = s;
    }

    // final states -> h_n, c_n
    constexpr size_t OUT0 = (size_t)BB * OO * HH;
    constexpr size_t HN   = (size_t)LL * BB * HH;
    for (int i = tid; i < 32 * HH; i += 320) {
        int m = i / HH, o = i - m * HH;
        int sb = m * SROWB + 2 * o;
        float hv = __half2float(*(__half*)(smem + hI + sb));
        float cv = __half2float(*(__half*)(smem + cI + sb));
        size_t off = ((size_t)l * BB + (r0 + m)) * HH + o;
        out[OUT0 + off]      = hv;
        out[OUT0 + HN + off] = cv;
    }
}

// ---------------- kernel 3: output projection ----------------
constexpr int YROW = TT * HH;  // 19968
constexpr int OSMEM = (YROW + OO * TT + OO) * 4;

__global__ __launch_bounds__(256) void out_kernel(const float* __restrict__ Wout,
                                                  const float* __restrict__ bout,
                                                  float* __restrict__ out) {
    extern __shared__ float sm[];
    float* sy = sm;
    float* sw = sm + YROW;
    float* sb = sw + OO * TT;
    const int b = blockIdx.x;
    const int tid = threadIdx.x;
    const float* yb = g_ys + (size_t)b * YROW;
    for (int i = tid; i < YROW / 4; i += 256) ((float4*)sy)[i] = ((const float4*)yb)[i];
    for (int i = tid; i < OO * TT; i += 256) sw[i] = Wout[i];
    if (tid < OO) sb[tid] = bout[tid];
    __syncthreads();
    for (int idx = tid; idx < HH * OO; idx += 256) {
        int f = idx / OO, jj = idx - f * OO;
        const float* yr = sy + f * TT;
        const float* wr = sw + jj * TT;
        float2 a = make_float2(0.f, 0.f);
#pragma unroll 4
        for (int p = 0; p < TT / 2; ++p)
            a = fma2(a, *(const float2*)(yr + 2 * p), *(const float2*)(wr + 2 * p));
        out[(size_t)b * (HH * OO) + idx] = a.x + a.y + sb[jj];
    }
}

// ---------------- launcher ----------------
extern "C" void kernel_launch(void* const* d_in, const int* in_sizes, int n_in,
                              void* d_out, int out_size) {
    const float* x   = (const float*)d_in[0];
    const float* adj = (const float*)d_in[1];

    XArgs xa;
    xa.W[0] = (const float*)d_in[2];  xa.bx[0] = (const float*)d_in[3];
    xa.W[1] = (const float*)d_in[6];  xa.bx[1] = (const float*)d_in[7];
    xa.W[2] = (const float*)d_in[10]; xa.bx[2] = (const float*)d_in[11];
    xa.W[3] = (const float*)d_in[14]; xa.bx[3] = (const float*)d_in[15];
    xa.bh[0] = (const float*)d_in[5];
    xa.bh[1] = (const float*)d_in[9];
    xa.bh[2] = (const float*)d_in[13];
    xa.bh[3] = (const float*)d_in[17];

    HArgs ha;
    ha.W[0] = (const float*)d_in[4];
    ha.W[1] = (const float*)d_in[8];
    ha.W[2] = (const float*)d_in[12];
    ha.W[3] = (const float*)d_in[16];

    const float* gw1  = (const float*)d_in[18];
    const float* gw2  = (const float*)d_in[19];
    const float* Wout = (const float*)d_in[20];
    const float* bout = (const float*)d_in[21];
    float* out = (float*)d_out;

    cudaFuncSetAttribute(recur_mma,  cudaFuncAttributeMaxDynamicSharedMemorySize, RSMEM2);
    cudaFuncSetAttribute(out_kernel, cudaFuncAttributeMaxDynamicSharedMemorySize, OSMEM);

    setup_bsum <<<(LL * NP + 255) / 256, 256>>>(xa);
    setup_adjf2<<<(20 * 10 * 32 + 255) / 256, 256>>>(adj);
    setup_wf2  <<<(LL * 80 * 10 * 32 + 255) / 256, 256>>>(ha);
    setup_wxf2 <<<(LL * 80 * 10 * 32 + 255) / 256, 256>>>(xa);

    dim3 rg(BB / 32, LL);                    // 128 x 2 = 256 blocks, 2/SM resident
    recur_mma<<<rg, 320, RSMEM2>>>(x, gw1, gw2, out);

    out_kernel<<<BB, 256, OSMEM>>>(Wout, bout, out);
}